// round 1
// baseline (speedup 1.0000x reference)
#include <cuda_runtime.h>
#include <cuda_bf16.h>

// Problem constants (fixed by the dataset)
#define NN 40000
#define EE 640000
#define GG 64
#define F1 128
#define F2 64

// ---------------- scratch (no allocations allowed) ----------------
__device__ float g_h [NN * F1];      // GEMM output / layer-2 input of agg
__device__ float g_hb[NN * F1];      // agg+LN output
__device__ float g_ss[NN];
__device__ float g_ds[NN];
__device__ int   g_deg[NN];
__device__ int   g_cnt2[NN];
__device__ int   g_rowptr[NN + 1];
__device__ int   g_csrsrc[EE];
__device__ float g_pool[GG * F2];
__device__ float g_pcnt[GG];

__device__ __forceinline__ float lrelu(float x) { return x > 0.f ? x : 0.2f * x; }

// ---------------- zero scratch ----------------
__global__ void zero_kernel() {
    int i = blockIdx.x * blockDim.x + threadIdx.x;
    if (i < NN) { g_deg[i] = 0; g_cnt2[i] = 0; }
    if (i < GG * F2) g_pool[i] = 0.f;
    if (i < GG) g_pcnt[i] = 0.f;
}

// ---------------- CSR build ----------------
__global__ void count_kernel(const int* __restrict__ dst) {
    int i = blockIdx.x * blockDim.x + threadIdx.x;
    if (i < EE) atomicAdd(&g_deg[dst[i]], 1);
}

__global__ void scan_kernel() {
    __shared__ int wsum[32];
    __shared__ int tot_s;
    int tid = threadIdx.x;
    int lane = tid & 31, wid = tid >> 5;
    int running = 0;
    for (int base = 0; base < NN; base += 1024) {
        int i = base + tid;
        int v = (i < NN) ? g_deg[i] : 0;
        int x = v;
        #pragma unroll
        for (int off = 1; off < 32; off <<= 1) {
            int y = __shfl_up_sync(0xffffffffu, x, off);
            if (lane >= off) x += y;
        }
        if (lane == 31) wsum[wid] = x;
        __syncthreads();
        if (wid == 0) {
            int w = wsum[lane];
            #pragma unroll
            for (int off = 1; off < 32; off <<= 1) {
                int y = __shfl_up_sync(0xffffffffu, w, off);
                if (lane >= off) w += y;
            }
            wsum[lane] = w;
        }
        __syncthreads();
        int add = (wid > 0) ? wsum[wid - 1] : 0;
        int incl = x + add;
        if (i < NN) g_rowptr[i] = running + incl - v;
        if (tid == 1023) tot_s = incl;
        __syncthreads();
        running += tot_s;
        __syncthreads();
    }
    if (tid == 0) g_rowptr[NN] = running;
}

__global__ void scatter_kernel(const int* __restrict__ src, const int* __restrict__ dst) {
    int i = blockIdx.x * blockDim.x + threadIdx.x;
    if (i < EE) {
        int d = dst[i];
        int p = g_rowptr[d] + atomicAdd(&g_cnt2[d], 1);
        g_csrsrc[p] = src[i];
    }
}

// ---------------- fp32 tiled GEMM: C[m][n] = sum_k A[m][k] * W[n][k] ----------------
// M multiple of 64, Nout multiple of 64, K multiple of 32.
__global__ void gemm_nt(const float* __restrict__ A, const float* __restrict__ W,
                        float* __restrict__ C, int M, int Nout, int K) {
    __shared__ float As[32][64];
    __shared__ float Ws[32][64];
    int tid = threadIdx.x;
    int tx = tid & 15, ty = tid >> 4;
    int mBase = blockIdx.x * 64;
    int nBase = blockIdx.y * 64;

    float acc[4][4];
    #pragma unroll
    for (int i = 0; i < 4; ++i)
        #pragma unroll
        for (int j = 0; j < 4; ++j) acc[i][j] = 0.f;

    for (int kt = 0; kt < K; kt += 32) {
        #pragma unroll
        for (int it = 0; it < 2; ++it) {
            int f = tid + it * 256;       // 0..511
            int row = f >> 3;
            int kc = (f & 7) * 4;
            float4 av = *(const float4*)&A[(size_t)(mBase + row) * K + kt + kc];
            As[kc + 0][row] = av.x; As[kc + 1][row] = av.y;
            As[kc + 2][row] = av.z; As[kc + 3][row] = av.w;
            float4 wv = *(const float4*)&W[(size_t)(nBase + row) * K + kt + kc];
            Ws[kc + 0][row] = wv.x; Ws[kc + 1][row] = wv.y;
            Ws[kc + 2][row] = wv.z; Ws[kc + 3][row] = wv.w;
        }
        __syncthreads();
        #pragma unroll
        for (int kk = 0; kk < 32; ++kk) {
            float4 a4 = *(const float4*)&As[kk][ty * 4];
            float4 b4 = *(const float4*)&Ws[kk][tx * 4];
            float a[4] = {a4.x, a4.y, a4.z, a4.w};
            float b[4] = {b4.x, b4.y, b4.z, b4.w};
            #pragma unroll
            for (int i = 0; i < 4; ++i)
                #pragma unroll
                for (int j = 0; j < 4; ++j) acc[i][j] += a[i] * b[j];
        }
        __syncthreads();
    }
    #pragma unroll
    for (int i = 0; i < 4; ++i) {
        float4 o = make_float4(acc[i][0], acc[i][1], acc[i][2], acc[i][3]);
        *(float4*)&C[(size_t)(mBase + ty * 4 + i) * Nout + nBase + tx * 4] = o;
    }
}

// ---------------- per-node attention scores ----------------
template <int F>
__global__ void scores_kernel(const float* __restrict__ h,
                              const float* __restrict__ asrc,
                              const float* __restrict__ adst) {
    int warp = (blockIdx.x * blockDim.x + threadIdx.x) >> 5;
    int lane = threadIdx.x & 31;
    if (warp >= NN) return;
    const float* hr = &h[(size_t)warp * F];
    float s1 = 0.f, s2 = 0.f;
    #pragma unroll
    for (int j = 0; j < F / 32; ++j) {
        float hv = hr[lane + 32 * j];
        s1 += hv * asrc[lane + 32 * j];
        s2 += hv * adst[lane + 32 * j];
    }
    #pragma unroll
    for (int off = 16; off > 0; off >>= 1) {
        s1 += __shfl_xor_sync(0xffffffffu, s1, off);
        s2 += __shfl_xor_sync(0xffffffffu, s2, off);
    }
    if (lane == 0) { g_ss[warp] = s1; g_ds[warp] = s2; }
}

// ---------------- fused GAT aggregate + bias + ReLU + LayerNorm ----------------
template <int F>
__global__ void agg_kernel(const float* __restrict__ h,
                           const float* __restrict__ bias,
                           const float* __restrict__ gamma,
                           const float* __restrict__ beta,
                           float* __restrict__ out) {
    constexpr int VPT = F / 32;
    int warp = (blockIdx.x * blockDim.x + threadIdx.x) >> 5;
    int lane = threadIdx.x & 31;
    if (warp >= NN) return;
    int n = warp;
    float dsn = g_ds[n];
    float eself = lrelu(g_ss[n] + dsn);
    int s0 = g_rowptr[n], s1 = g_rowptr[n + 1];

    // pass 1: max over incoming scores (incl self loop)
    float m = eself;
    for (int i = s0 + lane; i < s1; i += 32) {
        int s = g_csrsrc[i];
        m = fmaxf(m, lrelu(g_ss[s] + dsn));
    }
    #pragma unroll
    for (int off = 16; off > 0; off >>= 1)
        m = fmaxf(m, __shfl_xor_sync(0xffffffffu, m, off));

    // pass 2: weighted accumulate
    float acc[VPT];
    float w = __expf(eself - m);
    float z = w;
    const float* hn = &h[(size_t)n * F];
    #pragma unroll
    for (int j = 0; j < VPT; ++j) acc[j] = w * hn[lane + 32 * j];

    for (int i = s0; i < s1; ++i) {
        int s = g_csrsrc[i];
        float e = lrelu(g_ss[s] + dsn);
        float ww = __expf(e - m);
        z += ww;
        const float* hr = &h[(size_t)s * F];
        #pragma unroll
        for (int j = 0; j < VPT; ++j) acc[j] += ww * hr[lane + 32 * j];
    }

    float inv = 1.f / z;
    float v[VPT];
    float sum = 0.f;
    #pragma unroll
    for (int j = 0; j < VPT; ++j) {
        v[j] = fmaxf(acc[j] * inv + bias[lane + 32 * j], 0.f);  // bias + ReLU
        sum += v[j];
    }
    #pragma unroll
    for (int off = 16; off > 0; off >>= 1)
        sum += __shfl_xor_sync(0xffffffffu, sum, off);
    float mean = sum * (1.f / F);
    float vs = 0.f;
    #pragma unroll
    for (int j = 0; j < VPT; ++j) {
        float d = v[j] - mean;
        vs += d * d;
    }
    #pragma unroll
    for (int off = 16; off > 0; off >>= 1)
        vs += __shfl_xor_sync(0xffffffffu, vs, off);
    float var = vs * (1.f / F);
    float r = rsqrtf(var + 1e-5f);
    #pragma unroll
    for (int j = 0; j < VPT; ++j) {
        int f = lane + 32 * j;
        out[(size_t)n * F + f] = gamma[f] * (v[j] - mean) * r + beta[f];
    }
}

// ---------------- global mean pool (sums via atomics) ----------------
__global__ void pool_kernel(const float* __restrict__ h, const int* __restrict__ batch) {
    int warp = (blockIdx.x * blockDim.x + threadIdx.x) >> 5;
    int lane = threadIdx.x & 31;
    if (warp >= NN) return;
    int g = batch[warp];
    const float* hr = &h[(size_t)warp * F2];
    atomicAdd(&g_pool[g * F2 + lane], hr[lane]);
    atomicAdd(&g_pool[g * F2 + lane + 32], hr[lane + 32]);
    if (lane == 0) atomicAdd(&g_pcnt[g], 1.f);
}

// ---------------- head: mean, 64x64 linear, 64->1 linear ----------------
__global__ void head_kernel(const float* __restrict__ Wl, const float* __restrict__ bl,
                            const float* __restrict__ Wc, const float* __restrict__ bc,
                            float* __restrict__ out) {
    __shared__ float p[F2];
    __shared__ float red[2];
    int g = blockIdx.x;
    int t = threadIdx.x;
    float c = g_pcnt[g];
    p[t] = g_pool[g * F2 + t] / fmaxf(c, 1.f);
    __syncthreads();
    float lin = bl[t];
    #pragma unroll 8
    for (int j = 0; j < F2; ++j) lin += p[j] * Wl[t * F2 + j];
    float part = lin * Wc[t];
    #pragma unroll
    for (int off = 16; off > 0; off >>= 1)
        part += __shfl_xor_sync(0xffffffffu, part, off);
    if ((t & 31) == 0) red[t >> 5] = part;
    __syncthreads();
    if (t == 0) out[g] = red[0] + red[1] + bc[0];
}

// ---------------- launch ----------------
extern "C" void kernel_launch(void* const* d_in, const int* in_sizes, int n_in,
                              void* d_out, int out_size) {
    const float* x    = (const float*)d_in[0];
    const int*   ei   = (const int*)d_in[1];
    const int*   batch= (const int*)d_in[2];
    const float* W1   = (const float*)d_in[3];
    const float* a1s  = (const float*)d_in[4];
    const float* a1d  = (const float*)d_in[5];
    const float* b1   = (const float*)d_in[6];
    const float* g1   = (const float*)d_in[7];
    const float* be1  = (const float*)d_in[8];
    const float* W2   = (const float*)d_in[9];
    const float* a2s  = (const float*)d_in[10];
    const float* a2d  = (const float*)d_in[11];
    const float* b2   = (const float*)d_in[12];
    const float* g2   = (const float*)d_in[13];
    const float* be2  = (const float*)d_in[14];
    const float* Wl   = (const float*)d_in[15];
    const float* bl   = (const float*)d_in[16];
    const float* Wc   = (const float*)d_in[17];
    const float* bc   = (const float*)d_in[18];
    float* out = (float*)d_out;

    const int* src = ei;
    const int* dst = ei + EE;

    float *ph, *phb;
    cudaGetSymbolAddress((void**)&ph,  g_h);
    cudaGetSymbolAddress((void**)&phb, g_hb);

    // CSR build + zero scratch
    zero_kernel<<<(NN + 255) / 256, 256>>>();
    count_kernel<<<(EE + 255) / 256, 256>>>(dst);
    scan_kernel<<<1, 1024>>>();
    scatter_kernel<<<(EE + 255) / 256, 256>>>(src, dst);

    // layer 1
    gemm_nt<<<dim3(NN / 64, F1 / 64), 256>>>(x, W1, ph, NN, F1, 128);
    scores_kernel<F1><<<(NN * 32 + 255) / 256, 256>>>(ph, a1s, a1d);
    agg_kernel<F1><<<(NN * 32 + 255) / 256, 256>>>(ph, b1, g1, be1, phb);

    // layer 2
    gemm_nt<<<dim3(NN / 64, F2 / 64), 256>>>(phb, W2, ph, NN, F2, 128);
    scores_kernel<F2><<<(NN * 32 + 255) / 256, 256>>>(ph, a2s, a2d);
    agg_kernel<F2><<<(NN * 32 + 255) / 256, 256>>>(ph, b2, g2, be2, phb);

    // pool + head
    pool_kernel<<<(NN * 32 + 255) / 256, 256>>>(phb, batch);
    head_kernel<<<GG, F2>>>(Wl, bl, Wc, bc, out);
}

// round 2
// speedup vs baseline: 1.2501x; 1.2501x over previous
#include <cuda_runtime.h>
#include <cuda_bf16.h>

// Problem constants (fixed by the dataset)
#define NN 40000
#define EE 640000
#define GG 64
#define F1 128
#define F2 64

typedef unsigned long long ull;

// ---------------- scratch (no allocations allowed) ----------------
__device__ float g_h [NN * F1];      // GEMM output / layer input
__device__ float g_hb[NN * F1];      // agg+LN output
__device__ float g_ss[NN];
__device__ float g_ds[NN];
__device__ int   g_deg[NN];
__device__ int   g_cnt2[NN];
__device__ int   g_rowptr[NN + 1];
__device__ int   g_csrsrc[EE];
__device__ int   g_bsum[260];
__device__ float g_pool[GG * F2];
__device__ float g_pcnt[GG];

__device__ __forceinline__ float lrelu(float x) { return x > 0.f ? x : 0.2f * x; }

__device__ __forceinline__ void fma2(ull& d, ull a, ull b) {
    asm("fma.rn.f32x2 %0, %1, %2, %0;" : "+l"(d) : "l"(a), "l"(b));
}
__device__ __forceinline__ ull dup2(float x) {
    ull r; asm("mov.b64 %0, {%1, %1};" : "=l"(r) : "f"(x)); return r;
}
__device__ __forceinline__ void unpack2(ull v, float& lo, float& hi) {
    asm("mov.b64 {%0, %1}, %2;" : "=f"(lo), "=f"(hi) : "l"(v));
}

// ---------------- zero scratch ----------------
__global__ void zero_kernel() {
    int i = blockIdx.x * blockDim.x + threadIdx.x;
    if (i < NN) { g_deg[i] = 0; g_cnt2[i] = 0; }
    if (i < GG * F2) g_pool[i] = 0.f;
    if (i < GG) g_pcnt[i] = 0.f;
}

// ---------------- CSR build ----------------
__global__ void count_kernel(const int* __restrict__ dst) {
    int i = blockIdx.x * blockDim.x + threadIdx.x;
    if (i < EE) atomicAdd(&g_deg[dst[i]], 1);
}

__device__ __forceinline__ int block_excl_scan(int v) {
    __shared__ int ws[8];
    int tid = threadIdx.x;
    int lane = tid & 31, wid = tid >> 5;
    int x = v;
    #pragma unroll
    for (int off = 1; off < 32; off <<= 1) {
        int y = __shfl_up_sync(0xffffffffu, x, off);
        if (lane >= off) x += y;
    }
    if (lane == 31) ws[wid] = x;
    __syncthreads();
    if (wid == 0) {
        int w = (lane < 8) ? ws[lane] : 0;
        #pragma unroll
        for (int off = 1; off < 8; off <<= 1) {
            int y = __shfl_up_sync(0xffffffffu, w, off);
            if (lane >= off) w += y;
        }
        if (lane < 8) ws[lane] = w;
    }
    __syncthreads();
    int add = (wid > 0) ? ws[wid - 1] : 0;
    return x - v + add;   // exclusive
}

// local scan per 256-block; write local exclusive + block sums
__global__ void scan1_kernel() {
    int i = blockIdx.x * blockDim.x + threadIdx.x;
    int v = (i < NN) ? g_deg[i] : 0;
    int e = block_excl_scan(v);
    if (i < NN) g_rowptr[i] = e;
    if (threadIdx.x == 255) g_bsum[blockIdx.x] = e + v;
}

// scan the 157 block sums (single block)
__global__ void scan2_kernel(int nb) {
    int tid = threadIdx.x;
    int v = (tid < nb) ? g_bsum[tid] : 0;
    int e = block_excl_scan(v);
    g_bsum[tid] = e;
    if (tid == nb - 1) g_bsum[258] = e + v;   // grand total
}

__global__ void scan3_kernel() {
    int i = blockIdx.x * blockDim.x + threadIdx.x;
    if (i < NN) g_rowptr[i] += g_bsum[blockIdx.x];
    if (i == 0) g_rowptr[NN] = g_bsum[258];
}

__global__ void scatter_kernel(const int* __restrict__ src, const int* __restrict__ dst) {
    int i = blockIdx.x * blockDim.x + threadIdx.x;
    if (i < EE) {
        int d = dst[i];
        int p = g_rowptr[d] + atomicAdd(&g_cnt2[d], 1);
        g_csrsrc[p] = src[i];
    }
}

// ---------------- packed-f32x2 GEMM: C[m][n] = sum_k A[m][k] * W[n][k] ----------------
// BM=128, BN=64, BK=16, 256 threads, 8x4 per-thread tile (4 m-pairs x 4 n).
__global__ __launch_bounds__(256, 2)
void gemm_nt_f32x2(const float* __restrict__ A, const float* __restrict__ W,
                   float* __restrict__ C, int M, int Nout, int K) {
    __shared__ float As[16][132];   // stride 132: 16B-aligned rows, low-conflict stores
    __shared__ float Ws[16][68];

    int tid = threadIdx.x;
    int tx = tid & 15, ty = tid >> 4;
    int mBase = blockIdx.x * 128;
    int nBase = blockIdx.y * 64;
    int m0 = ty * 8, n0 = tx * 4;

    int arow = tid >> 2;            // 0..63 (second iter: +64)
    int akc  = (tid & 3) * 4;
    int wrow = tid >> 2;
    int wkc  = (tid & 3) * 4;

    ull acc[4][4];
    #pragma unroll
    for (int i = 0; i < 4; ++i)
        #pragma unroll
        for (int j = 0; j < 4; ++j) acc[i][j] = 0ull;

    float4 pa0, pa1, pw;
    auto loadA = [&](int kt, int it) -> float4 {
        int gr = mBase + arow + it * 64;
        if (gr < M) return *(const float4*)&A[(size_t)gr * K + kt + akc];
        return make_float4(0.f, 0.f, 0.f, 0.f);
    };
    auto loadW = [&](int kt) -> float4 {
        return *(const float4*)&W[(size_t)(nBase + wrow) * K + kt + wkc];
    };

    pa0 = loadA(0, 0); pa1 = loadA(0, 1); pw = loadW(0);

    for (int kt = 0; kt < K; kt += 16) {
        As[akc + 0][arow] = pa0.x; As[akc + 1][arow] = pa0.y;
        As[akc + 2][arow] = pa0.z; As[akc + 3][arow] = pa0.w;
        As[akc + 0][arow + 64] = pa1.x; As[akc + 1][arow + 64] = pa1.y;
        As[akc + 2][arow + 64] = pa1.z; As[akc + 3][arow + 64] = pa1.w;
        Ws[wkc + 0][wrow] = pw.x; Ws[wkc + 1][wrow] = pw.y;
        Ws[wkc + 2][wrow] = pw.z; Ws[wkc + 3][wrow] = pw.w;
        __syncthreads();

        if (kt + 16 < K) {
            pa0 = loadA(kt + 16, 0); pa1 = loadA(kt + 16, 1); pw = loadW(kt + 16);
        }

        #pragma unroll
        for (int kk = 0; kk < 16; ++kk) {
            ulonglong2 a01 = *(const ulonglong2*)&As[kk][m0];
            ulonglong2 a23 = *(const ulonglong2*)&As[kk][m0 + 4];
            float4 b = *(const float4*)&Ws[kk][n0];
            ull am[4] = {a01.x, a01.y, a23.x, a23.y};
            ull bd[4] = {dup2(b.x), dup2(b.y), dup2(b.z), dup2(b.w)};
            #pragma unroll
            for (int mp = 0; mp < 4; ++mp)
                #pragma unroll
                for (int n = 0; n < 4; ++n) fma2(acc[mp][n], am[mp], bd[n]);
        }
        __syncthreads();
    }

    #pragma unroll
    for (int mp = 0; mp < 4; ++mp) {
        float lo[4], hi[4];
        #pragma unroll
        for (int n = 0; n < 4; ++n) unpack2(acc[mp][n], lo[n], hi[n]);
        int r0 = mBase + m0 + 2 * mp;
        if (r0 < M)
            *(float4*)&C[(size_t)r0 * Nout + nBase + n0] = make_float4(lo[0], lo[1], lo[2], lo[3]);
        if (r0 + 1 < M)
            *(float4*)&C[(size_t)(r0 + 1) * Nout + nBase + n0] = make_float4(hi[0], hi[1], hi[2], hi[3]);
    }
}

// ---------------- per-node attention scores (vectorized) ----------------
template <int F>
__global__ void scores_kernel(const float* __restrict__ h,
                              const float* __restrict__ asrc,
                              const float* __restrict__ adst) {
    int warp = (blockIdx.x * blockDim.x + threadIdx.x) >> 5;
    int lane = threadIdx.x & 31;
    if (warp >= NN) return;
    float s1 = 0.f, s2 = 0.f;
    if constexpr (F == 128) {
        float4 hv = ((const float4*)&h[(size_t)warp * F])[lane];
        float4 a1 = ((const float4*)asrc)[lane];
        float4 a2 = ((const float4*)adst)[lane];
        s1 = hv.x * a1.x + hv.y * a1.y + hv.z * a1.z + hv.w * a1.w;
        s2 = hv.x * a2.x + hv.y * a2.y + hv.z * a2.z + hv.w * a2.w;
    } else {
        float2 hv = ((const float2*)&h[(size_t)warp * F])[lane];
        float2 a1 = ((const float2*)asrc)[lane];
        float2 a2 = ((const float2*)adst)[lane];
        s1 = hv.x * a1.x + hv.y * a1.y;
        s2 = hv.x * a2.x + hv.y * a2.y;
    }
    #pragma unroll
    for (int off = 16; off > 0; off >>= 1) {
        s1 += __shfl_xor_sync(0xffffffffu, s1, off);
        s2 += __shfl_xor_sync(0xffffffffu, s2, off);
    }
    if (lane == 0) { g_ss[warp] = s1; g_ds[warp] = s2; }
}

// ---------------- fused GAT aggregate + bias + ReLU + LayerNorm (vectorized) ----------------
template <int F>
__global__ void agg_kernel(const float* __restrict__ h,
                           const float* __restrict__ bias,
                           const float* __restrict__ gamma,
                           const float* __restrict__ beta,
                           float* __restrict__ out) {
    constexpr int VL = F / 32;
    int warp = (blockIdx.x * blockDim.x + threadIdx.x) >> 5;
    int lane = threadIdx.x & 31;
    if (warp >= NN) return;
    int n = warp;
    float dsn = g_ds[n];
    float eself = lrelu(g_ss[n] + dsn);
    int s0 = g_rowptr[n], s1 = g_rowptr[n + 1];

    // pass 1: max over incoming scores (incl self loop)
    float m = eself;
    for (int i = s0 + lane; i < s1; i += 32) {
        int s = g_csrsrc[i];
        m = fmaxf(m, lrelu(g_ss[s] + dsn));
    }
    #pragma unroll
    for (int off = 16; off > 0; off >>= 1)
        m = fmaxf(m, __shfl_xor_sync(0xffffffffu, m, off));

    // pass 2: weighted accumulate (2-edge unroll for MLP)
    float acc[VL];
    float w = __expf(eself - m);
    float z = w;
    if constexpr (VL == 4) {
        float4 t = ((const float4*)&h[(size_t)n * F])[lane];
        acc[0] = w * t.x; acc[1] = w * t.y; acc[2] = w * t.z; acc[3] = w * t.w;
    } else {
        float2 t = ((const float2*)&h[(size_t)n * F])[lane];
        acc[0] = w * t.x; acc[1] = w * t.y;
    }

    int i = s0;
    for (; i + 2 <= s1; i += 2) {
        int sa = g_csrsrc[i];
        int sb = g_csrsrc[i + 1];
        float ea = lrelu(g_ss[sa] + dsn);
        float eb = lrelu(g_ss[sb] + dsn);
        float wa = __expf(ea - m);
        float wb = __expf(eb - m);
        z += wa + wb;
        if constexpr (VL == 4) {
            float4 ta = ((const float4*)&h[(size_t)sa * F])[lane];
            float4 tb = ((const float4*)&h[(size_t)sb * F])[lane];
            acc[0] += wa * ta.x + wb * tb.x;
            acc[1] += wa * ta.y + wb * tb.y;
            acc[2] += wa * ta.z + wb * tb.z;
            acc[3] += wa * ta.w + wb * tb.w;
        } else {
            float2 ta = ((const float2*)&h[(size_t)sa * F])[lane];
            float2 tb = ((const float2*)&h[(size_t)sb * F])[lane];
            acc[0] += wa * ta.x + wb * tb.x;
            acc[1] += wa * ta.y + wb * tb.y;
        }
    }
    if (i < s1) {
        int s = g_csrsrc[i];
        float e = lrelu(g_ss[s] + dsn);
        float ww = __expf(e - m);
        z += ww;
        if constexpr (VL == 4) {
            float4 t = ((const float4*)&h[(size_t)s * F])[lane];
            acc[0] += ww * t.x; acc[1] += ww * t.y; acc[2] += ww * t.z; acc[3] += ww * t.w;
        } else {
            float2 t = ((const float2*)&h[(size_t)s * F])[lane];
            acc[0] += ww * t.x; acc[1] += ww * t.y;
        }
    }

    float inv = 1.f / z;
    float v[VL];
    float sum = 0.f;
    #pragma unroll
    for (int j = 0; j < VL; ++j) {
        v[j] = fmaxf(acc[j] * inv + bias[lane * VL + j], 0.f);  // bias + ReLU
        sum += v[j];
    }
    #pragma unroll
    for (int off = 16; off > 0; off >>= 1)
        sum += __shfl_xor_sync(0xffffffffu, sum, off);
    float mean = sum * (1.f / F);
    float vs = 0.f;
    #pragma unroll
    for (int j = 0; j < VL; ++j) {
        float d = v[j] - mean;
        vs += d * d;
    }
    #pragma unroll
    for (int off = 16; off > 0; off >>= 1)
        vs += __shfl_xor_sync(0xffffffffu, vs, off);
    float var = vs * (1.f / F);
    float r = rsqrtf(var + 1e-5f);
    if constexpr (VL == 4) {
        float4 gv = ((const float4*)gamma)[lane];
        float4 bv = ((const float4*)beta)[lane];
        float4 o;
        o.x = gv.x * (v[0] - mean) * r + bv.x;
        o.y = gv.y * (v[1] - mean) * r + bv.y;
        o.z = gv.z * (v[2] - mean) * r + bv.z;
        o.w = gv.w * (v[3] - mean) * r + bv.w;
        ((float4*)&out[(size_t)n * F])[lane] = o;
    } else {
        float2 gv = ((const float2*)gamma)[lane];
        float2 bv = ((const float2*)beta)[lane];
        float2 o;
        o.x = gv.x * (v[0] - mean) * r + bv.x;
        o.y = gv.y * (v[1] - mean) * r + bv.y;
        ((float2*)&out[(size_t)n * F])[lane] = o;
    }
}

// ---------------- global mean pool (sums via atomics) ----------------
__global__ void pool_kernel(const float* __restrict__ h, const int* __restrict__ batch) {
    int warp = (blockIdx.x * blockDim.x + threadIdx.x) >> 5;
    int lane = threadIdx.x & 31;
    if (warp >= NN) return;
    int g = batch[warp];
    const float* hr = &h[(size_t)warp * F2];
    atomicAdd(&g_pool[g * F2 + lane], hr[lane]);
    atomicAdd(&g_pool[g * F2 + lane + 32], hr[lane + 32]);
    if (lane == 0) atomicAdd(&g_pcnt[g], 1.f);
}

// ---------------- head: mean, 64x64 linear, 64->1 linear ----------------
__global__ void head_kernel(const float* __restrict__ Wl, const float* __restrict__ bl,
                            const float* __restrict__ Wc, const float* __restrict__ bc,
                            float* __restrict__ out) {
    __shared__ float p[F2];
    __shared__ float red[2];
    int g = blockIdx.x;
    int t = threadIdx.x;
    float c = g_pcnt[g];
    p[t] = g_pool[g * F2 + t] / fmaxf(c, 1.f);
    __syncthreads();
    float lin = bl[t];
    #pragma unroll 8
    for (int j = 0; j < F2; ++j) lin += p[j] * Wl[t * F2 + j];
    float part = lin * Wc[t];
    #pragma unroll
    for (int off = 16; off > 0; off >>= 1)
        part += __shfl_xor_sync(0xffffffffu, part, off);
    if ((t & 31) == 0) red[t >> 5] = part;
    __syncthreads();
    if (t == 0) out[g] = red[0] + red[1] + bc[0];
}

// ---------------- launch ----------------
extern "C" void kernel_launch(void* const* d_in, const int* in_sizes, int n_in,
                              void* d_out, int out_size) {
    const float* x    = (const float*)d_in[0];
    const int*   ei   = (const int*)d_in[1];
    const int*   batch= (const int*)d_in[2];
    const float* W1   = (const float*)d_in[3];
    const float* a1s  = (const float*)d_in[4];
    const float* a1d  = (const float*)d_in[5];
    const float* b1   = (const float*)d_in[6];
    const float* g1   = (const float*)d_in[7];
    const float* be1  = (const float*)d_in[8];
    const float* W2   = (const float*)d_in[9];
    const float* a2s  = (const float*)d_in[10];
    const float* a2d  = (const float*)d_in[11];
    const float* b2   = (const float*)d_in[12];
    const float* g2   = (const float*)d_in[13];
    const float* be2  = (const float*)d_in[14];
    const float* Wl   = (const float*)d_in[15];
    const float* bl   = (const float*)d_in[16];
    const float* Wc   = (const float*)d_in[17];
    const float* bc   = (const float*)d_in[18];
    float* out = (float*)d_out;

    const int* src = ei;
    const int* dst = ei + EE;

    float *ph, *phb;
    cudaGetSymbolAddress((void**)&ph,  g_h);
    cudaGetSymbolAddress((void**)&phb, g_hb);

    const int NB = (NN + 255) / 256;   // 157

    // CSR build + zero scratch
    zero_kernel<<<NB, 256>>>();
    count_kernel<<<(EE + 255) / 256, 256>>>(dst);
    scan1_kernel<<<NB, 256>>>();
    scan2_kernel<<<1, 256>>>(NB);
    scan3_kernel<<<NB, 256>>>();
    scatter_kernel<<<(EE + 255) / 256, 256>>>(src, dst);

    // layer 1
    gemm_nt_f32x2<<<dim3((NN + 127) / 128, F1 / 64), 256>>>(x, W1, ph, NN, F1, 128);
    scores_kernel<F1><<<(NN * 32 + 255) / 256, 256>>>(ph, a1s, a1d);
    agg_kernel<F1><<<(NN * 32 + 255) / 256, 256>>>(ph, b1, g1, be1, phb);

    // layer 2
    gemm_nt_f32x2<<<dim3((NN + 127) / 128, F2 / 64), 256>>>(phb, W2, ph, NN, F2, 128);
    scores_kernel<F2><<<(NN * 32 + 255) / 256, 256>>>(ph, a2s, a2d);
    agg_kernel<F2><<<(NN * 32 + 255) / 256, 256>>>(ph, b2, g2, be2, phb);

    // pool + head
    pool_kernel<<<(NN * 32 + 255) / 256, 256>>>(phb, batch);
    head_kernel<<<GG, F2>>>(Wl, bl, Wc, bc, out);
}

// round 3
// speedup vs baseline: 1.5146x; 1.2116x over previous
#include <cuda_runtime.h>
#include <cuda_bf16.h>

// Problem constants (fixed by the dataset)
#define NN 40000
#define EE 640000
#define GG 64
#define F1 128
#define F2 64

typedef unsigned long long ull;

// ---------------- scratch (no allocations allowed) ----------------
__device__ float g_h [NN * F1];      // GEMM output / layer input
__device__ float g_hb[NN * F1];      // agg+LN output
__device__ float g_ss[NN];
__device__ float g_ds[NN];
__device__ int   g_deg[NN];
__device__ int   g_cnt2[NN];
__device__ int   g_rowptr[NN + 1];
__device__ int   g_csrsrc[EE];
__device__ int   g_bsum[260];
__device__ float g_pool[GG * F2];
__device__ float g_pcnt[GG];

__device__ __forceinline__ float lrelu(float x) { return x > 0.f ? x : 0.2f * x; }

__device__ __forceinline__ void fma2(ull& d, ull a, ull b) {
    asm("fma.rn.f32x2 %0, %1, %2, %0;" : "+l"(d) : "l"(a), "l"(b));
}
__device__ __forceinline__ ull dup2(float x) {
    ull r; asm("mov.b64 %0, {%1, %1};" : "=l"(r) : "f"(x)); return r;
}
__device__ __forceinline__ void unpack2(ull v, float& lo, float& hi) {
    asm("mov.b64 {%0, %1}, %2;" : "=f"(lo), "=f"(hi) : "l"(v));
}

// ---------------- zero scratch ----------------
__global__ void zero_kernel() {
    int i = blockIdx.x * blockDim.x + threadIdx.x;
    if (i < NN) { g_deg[i] = 0; g_cnt2[i] = 0; }
    if (i < GG * F2) g_pool[i] = 0.f;
    if (i < GG) g_pcnt[i] = 0.f;
}

// ---------------- CSR build ----------------
__global__ void count_kernel(const int* __restrict__ dst) {
    int i = blockIdx.x * blockDim.x + threadIdx.x;
    if (i < EE) atomicAdd(&g_deg[dst[i]], 1);
}

__device__ __forceinline__ int block_excl_scan(int v) {
    __shared__ int ws[8];
    int tid = threadIdx.x;
    int lane = tid & 31, wid = tid >> 5;
    int x = v;
    #pragma unroll
    for (int off = 1; off < 32; off <<= 1) {
        int y = __shfl_up_sync(0xffffffffu, x, off);
        if (lane >= off) x += y;
    }
    if (lane == 31) ws[wid] = x;
    __syncthreads();
    if (wid == 0) {
        int w = (lane < 8) ? ws[lane] : 0;
        #pragma unroll
        for (int off = 1; off < 8; off <<= 1) {
            int y = __shfl_up_sync(0xffffffffu, w, off);
            if (lane >= off) w += y;
        }
        if (lane < 8) ws[lane] = w;
    }
    __syncthreads();
    int add = (wid > 0) ? ws[wid - 1] : 0;
    return x - v + add;   // exclusive
}

// local scan per 256-block; write local exclusive + block sums
__global__ void scan1_kernel() {
    int i = blockIdx.x * blockDim.x + threadIdx.x;
    int v = (i < NN) ? g_deg[i] : 0;
    int e = block_excl_scan(v);
    if (i < NN) g_rowptr[i] = e;
    if (threadIdx.x == 255) g_bsum[blockIdx.x] = e + v;
}

// each block computes its own prefix over block sums (nb <= 256), adds offset
__global__ void scan3_kernel(int nb) {
    __shared__ int wsum[8];
    int b = blockIdx.x;
    int t = threadIdx.x;
    int lane = t & 31, wid = t >> 5;
    int v = (t < b) ? g_bsum[t] : 0;
    #pragma unroll
    for (int off = 16; off > 0; off >>= 1) v += __shfl_xor_sync(0xffffffffu, v, off);
    if (lane == 0) wsum[wid] = v;
    __syncthreads();
    int total;
    {
        int w = wsum[lane & 7];
        #pragma unroll
        for (int off = 4; off > 0; off >>= 1) w += __shfl_xor_sync(0xffffffffu, w, off);
        total = w;  // sum of bsum[0..b-1]
    }
    int i = b * 256 + t;
    if (i < NN) g_rowptr[i] += total;
    if (b == nb - 1 && t == 0) g_rowptr[NN] = total + g_bsum[nb - 1];
}

__global__ void scatter_kernel(const int* __restrict__ src, const int* __restrict__ dst) {
    int i = blockIdx.x * blockDim.x + threadIdx.x;
    if (i < EE) {
        int d = dst[i];
        int p = g_rowptr[d] + atomicAdd(&g_cnt2[d], 1);
        g_csrsrc[p] = src[i];
    }
}

// ---------------- packed-f32x2 GEMM: C[m][n] = sum_k A[m][k] * W[n][k] ----------------
// BM=128, BN=64, BK=16, 128 threads, per-thread 8m(4 f32x2 pairs) x 8n.
__global__ __launch_bounds__(128)
void gemm_nt_f32x2(const float* __restrict__ A, const float* __restrict__ W,
                   float* __restrict__ C, int M, int Nout, int K) {
    __shared__ float As[16][132];
    __shared__ float Ws[16][68];

    int tid = threadIdx.x;
    int tx = tid & 7, ty = tid >> 3;        // ty 0..15, tx 0..7
    int mBase = blockIdx.x * 128;
    int nBase = blockIdx.y * 64;
    int m0 = ty * 8, n0 = tx * 8;

    int lrow = tid >> 2;                    // 0..31
    int lkc  = (tid & 3) * 4;

    ull acc[4][8];
    #pragma unroll
    for (int i = 0; i < 4; ++i)
        #pragma unroll
        for (int j = 0; j < 8; ++j) acc[i][j] = 0ull;

    float4 pa[4], pw[2];
    auto loadA = [&](int kt) {
        #pragma unroll
        for (int i = 0; i < 4; ++i) {
            int gr = mBase + lrow + i * 32;
            pa[i] = (gr < M) ? *(const float4*)&A[(size_t)gr * K + kt + lkc]
                             : make_float4(0.f, 0.f, 0.f, 0.f);
        }
    };
    auto loadW = [&](int kt) {
        #pragma unroll
        for (int i = 0; i < 2; ++i)
            pw[i] = *(const float4*)&W[(size_t)(nBase + lrow + i * 32) * K + kt + lkc];
    };

    loadA(0); loadW(0);

    for (int kt = 0; kt < K; kt += 16) {
        #pragma unroll
        for (int i = 0; i < 4; ++i) {
            int r = lrow + i * 32;
            As[lkc + 0][r] = pa[i].x; As[lkc + 1][r] = pa[i].y;
            As[lkc + 2][r] = pa[i].z; As[lkc + 3][r] = pa[i].w;
        }
        #pragma unroll
        for (int i = 0; i < 2; ++i) {
            int r = lrow + i * 32;
            Ws[lkc + 0][r] = pw[i].x; Ws[lkc + 1][r] = pw[i].y;
            Ws[lkc + 2][r] = pw[i].z; Ws[lkc + 3][r] = pw[i].w;
        }
        __syncthreads();

        if (kt + 16 < K) { loadA(kt + 16); loadW(kt + 16); }

        #pragma unroll
        for (int kk = 0; kk < 16; ++kk) {
            ulonglong2 a01 = *(const ulonglong2*)&As[kk][m0];
            ulonglong2 a23 = *(const ulonglong2*)&As[kk][m0 + 4];
            float4 b0 = *(const float4*)&Ws[kk][n0];
            float4 b1 = *(const float4*)&Ws[kk][n0 + 4];
            ull am[4] = {a01.x, a01.y, a23.x, a23.y};
            ull bd[8] = {dup2(b0.x), dup2(b0.y), dup2(b0.z), dup2(b0.w),
                         dup2(b1.x), dup2(b1.y), dup2(b1.z), dup2(b1.w)};
            #pragma unroll
            for (int mp = 0; mp < 4; ++mp)
                #pragma unroll
                for (int n = 0; n < 8; ++n) fma2(acc[mp][n], am[mp], bd[n]);
        }
        __syncthreads();
    }

    #pragma unroll
    for (int mp = 0; mp < 4; ++mp) {
        float lo[8], hi[8];
        #pragma unroll
        for (int n = 0; n < 8; ++n) unpack2(acc[mp][n], lo[n], hi[n]);
        int r0 = mBase + m0 + 2 * mp;
        if (r0 < M) {
            *(float4*)&C[(size_t)r0 * Nout + nBase + n0]     = make_float4(lo[0], lo[1], lo[2], lo[3]);
            *(float4*)&C[(size_t)r0 * Nout + nBase + n0 + 4] = make_float4(lo[4], lo[5], lo[6], lo[7]);
        }
        if (r0 + 1 < M) {
            *(float4*)&C[(size_t)(r0 + 1) * Nout + nBase + n0]     = make_float4(hi[0], hi[1], hi[2], hi[3]);
            *(float4*)&C[(size_t)(r0 + 1) * Nout + nBase + n0 + 4] = make_float4(hi[4], hi[5], hi[6], hi[7]);
        }
    }
}

// ---------------- per-node attention scores (vectorized) ----------------
template <int F>
__global__ void scores_kernel(const float* __restrict__ h,
                              const float* __restrict__ asrc,
                              const float* __restrict__ adst) {
    int warp = (blockIdx.x * blockDim.x + threadIdx.x) >> 5;
    int lane = threadIdx.x & 31;
    if (warp >= NN) return;
    float s1 = 0.f, s2 = 0.f;
    if constexpr (F == 128) {
        float4 hv = ((const float4*)&h[(size_t)warp * F])[lane];
        float4 a1 = ((const float4*)asrc)[lane];
        float4 a2 = ((const float4*)adst)[lane];
        s1 = hv.x * a1.x + hv.y * a1.y + hv.z * a1.z + hv.w * a1.w;
        s2 = hv.x * a2.x + hv.y * a2.y + hv.z * a2.z + hv.w * a2.w;
    } else {
        float2 hv = ((const float2*)&h[(size_t)warp * F])[lane];
        float2 a1 = ((const float2*)asrc)[lane];
        float2 a2 = ((const float2*)adst)[lane];
        s1 = hv.x * a1.x + hv.y * a1.y;
        s2 = hv.x * a2.x + hv.y * a2.y;
    }
    #pragma unroll
    for (int off = 16; off > 0; off >>= 1) {
        s1 += __shfl_xor_sync(0xffffffffu, s1, off);
        s2 += __shfl_xor_sync(0xffffffffu, s2, off);
    }
    if (lane == 0) { g_ss[warp] = s1; g_ds[warp] = s2; }
}

// ---------------- fused GAT aggregate + bias + ReLU + LayerNorm ----------------
// single pass: softmax is shift-invariant and scores are O(1), so no max pass.
template <int F>
__global__ void agg_kernel(const float* __restrict__ h,
                           const float* __restrict__ bias,
                           const float* __restrict__ gamma,
                           const float* __restrict__ beta,
                           float* __restrict__ out) {
    constexpr int VL = F / 32;
    int warp = (blockIdx.x * blockDim.x + threadIdx.x) >> 5;
    int lane = threadIdx.x & 31;
    if (warp >= NN) return;
    int n = warp;
    float dsn = g_ds[n];
    int s0 = g_rowptr[n], s1 = g_rowptr[n + 1];

    float acc[VL];
    float w = __expf(lrelu(g_ss[n] + dsn));   // self loop
    float z = w;
    if constexpr (VL == 4) {
        float4 t = ((const float4*)&h[(size_t)n * F])[lane];
        acc[0] = w * t.x; acc[1] = w * t.y; acc[2] = w * t.z; acc[3] = w * t.w;
    } else {
        float2 t = ((const float2*)&h[(size_t)n * F])[lane];
        acc[0] = w * t.x; acc[1] = w * t.y;
    }

    int i = s0;
    for (; i + 2 <= s1; i += 2) {
        int sa = g_csrsrc[i];
        int sb = g_csrsrc[i + 1];
        float wa = __expf(lrelu(g_ss[sa] + dsn));
        float wb = __expf(lrelu(g_ss[sb] + dsn));
        z += wa + wb;
        if constexpr (VL == 4) {
            float4 ta = ((const float4*)&h[(size_t)sa * F])[lane];
            float4 tb = ((const float4*)&h[(size_t)sb * F])[lane];
            acc[0] += wa * ta.x + wb * tb.x;
            acc[1] += wa * ta.y + wb * tb.y;
            acc[2] += wa * ta.z + wb * tb.z;
            acc[3] += wa * ta.w + wb * tb.w;
        } else {
            float2 ta = ((const float2*)&h[(size_t)sa * F])[lane];
            float2 tb = ((const float2*)&h[(size_t)sb * F])[lane];
            acc[0] += wa * ta.x + wb * tb.x;
            acc[1] += wa * ta.y + wb * tb.y;
        }
    }
    if (i < s1) {
        int s = g_csrsrc[i];
        float ww = __expf(lrelu(g_ss[s] + dsn));
        z += ww;
        if constexpr (VL == 4) {
            float4 t = ((const float4*)&h[(size_t)s * F])[lane];
            acc[0] += ww * t.x; acc[1] += ww * t.y; acc[2] += ww * t.z; acc[3] += ww * t.w;
        } else {
            float2 t = ((const float2*)&h[(size_t)s * F])[lane];
            acc[0] += ww * t.x; acc[1] += ww * t.y;
        }
    }

    float inv = 1.f / z;
    float v[VL];
    float sum = 0.f;
    #pragma unroll
    for (int j = 0; j < VL; ++j) {
        v[j] = fmaxf(acc[j] * inv + bias[lane * VL + j], 0.f);  // bias + ReLU
        sum += v[j];
    }
    #pragma unroll
    for (int off = 16; off > 0; off >>= 1)
        sum += __shfl_xor_sync(0xffffffffu, sum, off);
    float mean = sum * (1.f / F);
    float vs = 0.f;
    #pragma unroll
    for (int j = 0; j < VL; ++j) {
        float d = v[j] - mean;
        vs += d * d;
    }
    #pragma unroll
    for (int off = 16; off > 0; off >>= 1)
        vs += __shfl_xor_sync(0xffffffffu, vs, off);
    float var = vs * (1.f / F);
    float r = rsqrtf(var + 1e-5f);
    if constexpr (VL == 4) {
        float4 gv = ((const float4*)gamma)[lane];
        float4 bv = ((const float4*)beta)[lane];
        float4 o;
        o.x = gv.x * (v[0] - mean) * r + bv.x;
        o.y = gv.y * (v[1] - mean) * r + bv.y;
        o.z = gv.z * (v[2] - mean) * r + bv.z;
        o.w = gv.w * (v[3] - mean) * r + bv.w;
        ((float4*)&out[(size_t)n * F])[lane] = o;
    } else {
        float2 gv = ((const float2*)gamma)[lane];
        float2 bv = ((const float2*)beta)[lane];
        float2 o;
        o.x = gv.x * (v[0] - mean) * r + bv.x;
        o.y = gv.y * (v[1] - mean) * r + bv.y;
        ((float2*)&out[(size_t)n * F])[lane] = o;
    }
}

// ---------------- global mean pool: run-length accumulate (batch is sorted) ----------------
// grid = NN/64 blocks, 256 threads; thread (q, f): q = tid>>6 handles 16 nodes, feature f.
__global__ void pool_kernel(const float* __restrict__ h, const int* __restrict__ batch) {
    int b = blockIdx.x;
    int f = threadIdx.x & 63;
    int q = threadIdx.x >> 6;
    int n0 = b * 64 + q * 16;
    float acc = 0.f;
    float cnt = 0.f;
    int curg = batch[n0];
    #pragma unroll 4
    for (int i = 0; i < 16; ++i) {
        int n = n0 + i;
        int g = batch[n];
        if (g != curg) {
            atomicAdd(&g_pool[curg * F2 + f], acc);
            if (f == 0) atomicAdd(&g_pcnt[curg], cnt);
            acc = 0.f; cnt = 0.f; curg = g;
        }
        acc += h[(size_t)n * F2 + f];
        cnt += 1.f;
    }
    atomicAdd(&g_pool[curg * F2 + f], acc);
    if (f == 0) atomicAdd(&g_pcnt[curg], cnt);
}

// ---------------- head: mean, 64x64 linear, 64->1 linear ----------------
__global__ void head_kernel(const float* __restrict__ Wl, const float* __restrict__ bl,
                            const float* __restrict__ Wc, const float* __restrict__ bc,
                            float* __restrict__ out) {
    __shared__ float p[F2];
    __shared__ float red[2];
    int g = blockIdx.x;
    int t = threadIdx.x;
    float c = g_pcnt[g];
    p[t] = g_pool[g * F2 + t] / fmaxf(c, 1.f);
    __syncthreads();
    float lin = bl[t];
    #pragma unroll 8
    for (int j = 0; j < F2; ++j) lin += p[j] * Wl[t * F2 + j];
    float part = lin * Wc[t];
    #pragma unroll
    for (int off = 16; off > 0; off >>= 1)
        part += __shfl_xor_sync(0xffffffffu, part, off);
    if ((t & 31) == 0) red[t >> 5] = part;
    __syncthreads();
    if (t == 0) out[g] = red[0] + red[1] + bc[0];
}

// ---------------- launch ----------------
extern "C" void kernel_launch(void* const* d_in, const int* in_sizes, int n_in,
                              void* d_out, int out_size) {
    const float* x    = (const float*)d_in[0];
    const int*   ei   = (const int*)d_in[1];
    const int*   batch= (const int*)d_in[2];
    const float* W1   = (const float*)d_in[3];
    const float* a1s  = (const float*)d_in[4];
    const float* a1d  = (const float*)d_in[5];
    const float* b1   = (const float*)d_in[6];
    const float* g1   = (const float*)d_in[7];
    const float* be1  = (const float*)d_in[8];
    const float* W2   = (const float*)d_in[9];
    const float* a2s  = (const float*)d_in[10];
    const float* a2d  = (const float*)d_in[11];
    const float* b2   = (const float*)d_in[12];
    const float* g2   = (const float*)d_in[13];
    const float* be2  = (const float*)d_in[14];
    const float* Wl   = (const float*)d_in[15];
    const float* bl   = (const float*)d_in[16];
    const float* Wc   = (const float*)d_in[17];
    const float* bc   = (const float*)d_in[18];
    float* out = (float*)d_out;

    const int* src = ei;
    const int* dst = ei + EE;

    float *ph, *phb;
    cudaGetSymbolAddress((void**)&ph,  g_h);
    cudaGetSymbolAddress((void**)&phb, g_hb);

    const int NB = (NN + 255) / 256;   // 157

    // CSR build + zero scratch
    zero_kernel<<<NB, 256>>>();
    count_kernel<<<(EE + 255) / 256, 256>>>(dst);
    scan1_kernel<<<NB, 256>>>();
    scan3_kernel<<<NB, 256>>>(NB);
    scatter_kernel<<<(EE + 255) / 256, 256>>>(src, dst);

    // layer 1
    gemm_nt_f32x2<<<dim3((NN + 127) / 128, F1 / 64), 128>>>(x, W1, ph, NN, F1, 128);
    scores_kernel<F1><<<(NN * 32 + 255) / 256, 256>>>(ph, a1s, a1d);
    agg_kernel<F1><<<(NN * 32 + 255) / 256, 256>>>(ph, b1, g1, be1, phb);

    // layer 2
    gemm_nt_f32x2<<<dim3((NN + 127) / 128, F2 / 64), 128>>>(phb, W2, ph, NN, F2, 128);
    scores_kernel<F2><<<(NN * 32 + 255) / 256, 256>>>(ph, a2s, a2d);
    agg_kernel<F2><<<(NN * 32 + 255) / 256, 256>>>(ph, b2, g2, be2, phb);

    // pool + head
    pool_kernel<<<NN / 64, 256>>>(phb, batch);
    head_kernel<<<GG, F2>>>(Wl, bl, Wc, bc, out);
}

// round 4
// speedup vs baseline: 1.5176x; 1.0020x over previous
#include <cuda_runtime.h>
#include <cuda_bf16.h>

// Problem constants (fixed by the dataset)
#define NN 40000
#define EE 640000
#define GG 64
#define F1 128
#define F2 64

typedef unsigned long long ull;

// ---------------- scratch (no allocations allowed) ----------------
__device__ __nv_bfloat16 g_hbf[NN * F1];  // GEMM output (bf16) for gathers
__device__ float g_hb[NN * F1];           // agg+LN output (fp32, feeds next GEMM / pool)
__device__ float g_ss1[NN], g_ds1[NN];
__device__ float g_ss2[NN], g_ds2[NN];
__device__ int   g_deg[NN];
__device__ int   g_cnt2[NN];
__device__ int   g_rowptr[NN + 1];
__device__ int   g_csrsrc[EE];
__device__ float g_pool[GG * F2];
__device__ float g_pcnt[GG];

__device__ __forceinline__ float lrelu(float x) { return x > 0.f ? x : 0.2f * x; }

__device__ __forceinline__ void fma2(ull& d, ull a, ull b) {
    asm("fma.rn.f32x2 %0, %1, %2, %0;" : "+l"(d) : "l"(a), "l"(b));
}
__device__ __forceinline__ ull dup2(float x) {
    ull r; asm("mov.b64 %0, {%1, %1};" : "=l"(r) : "f"(x)); return r;
}
__device__ __forceinline__ void unpack2(ull v, float& lo, float& hi) {
    asm("mov.b64 {%0, %1}, %2;" : "=f"(lo), "=f"(hi) : "l"(v));
}

// ---------------- zero scratch ----------------
__global__ void zero_kernel() {
    int i = blockIdx.x * blockDim.x + threadIdx.x;
    if (i < NN) {
        g_deg[i] = 0; g_cnt2[i] = 0;
        g_ss1[i] = 0.f; g_ds1[i] = 0.f;
        g_ss2[i] = 0.f; g_ds2[i] = 0.f;
    }
    if (i < GG * F2) g_pool[i] = 0.f;
    if (i < GG) g_pcnt[i] = 0.f;
}

// ---------------- CSR build ----------------
__global__ void count_kernel(const int* __restrict__ dst) {
    int i = blockIdx.x * blockDim.x + threadIdx.x;
    if (i < EE) atomicAdd(&g_deg[dst[i]], 1);
}

__device__ __forceinline__ int block_excl_scan(int v) {
    __shared__ int ws[8];
    int tid = threadIdx.x;
    int lane = tid & 31, wid = tid >> 5;
    int x = v;
    #pragma unroll
    for (int off = 1; off < 32; off <<= 1) {
        int y = __shfl_up_sync(0xffffffffu, x, off);
        if (lane >= off) x += y;
    }
    if (lane == 31) ws[wid] = x;
    __syncthreads();
    if (wid == 0) {
        int w = (lane < 8) ? ws[lane] : 0;
        #pragma unroll
        for (int off = 1; off < 8; off <<= 1) {
            int y = __shfl_up_sync(0xffffffffu, w, off);
            if (lane >= off) w += y;
        }
        if (lane < 8) ws[lane] = w;
    }
    __syncthreads();
    int add = (wid > 0) ? ws[wid - 1] : 0;
    return x - v + add;   // exclusive
}

// one-launch scan: each block recomputes its global offset itself
__global__ void scan_kernel() {
    __shared__ int red[8];
    __shared__ int s_off;
    int b = blockIdx.x, t = threadIdx.x;
    int lane = t & 31, wid = t >> 5;
    // offset = sum deg[0 .. b*256)
    int lim = b * 256;
    int part = 0;
    for (int j = t; j < lim; j += 256) part += g_deg[j];
    #pragma unroll
    for (int off = 16; off > 0; off >>= 1) part += __shfl_xor_sync(0xffffffffu, part, off);
    if (lane == 0) red[wid] = part;
    __syncthreads();
    if (t == 0) {
        int s = 0;
        #pragma unroll
        for (int k = 0; k < 8; ++k) s += red[k];
        s_off = s;
    }
    __syncthreads();
    int off0 = s_off;
    int i = b * 256 + t;
    int v = (i < NN) ? g_deg[i] : 0;
    int e = block_excl_scan(v);
    if (i < NN) g_rowptr[i] = off0 + e;
    if (i == NN - 1) g_rowptr[NN] = off0 + e + v;
}

__global__ void scatter_kernel(const int* __restrict__ src, const int* __restrict__ dst) {
    int i = blockIdx.x * blockDim.x + threadIdx.x;
    if (i < EE) {
        int d = dst[i];
        int p = g_rowptr[d] + atomicAdd(&g_cnt2[d], 1);
        g_csrsrc[p] = src[i];
    }
}

// ---------------- packed-f32x2 GEMM with fused score epilogue ----------------
// C row stored as bf16; ss/ds accumulated via atomics (fp32 accumulator dots).
// BM=128, BN=64, BK=16, 128 threads, per-thread 8m(4 f32x2 pairs) x 8n.
__global__ __launch_bounds__(128)
void gemm_nt_f32x2(const float* __restrict__ A, const float* __restrict__ W,
                   __nv_bfloat16* __restrict__ Cb,
                   float* __restrict__ ss, float* __restrict__ ds,
                   const float* __restrict__ asrc, const float* __restrict__ adst,
                   int M, int Nout, int K) {
    __shared__ float As[16][132];
    __shared__ float Ws[16][68];

    int tid = threadIdx.x;
    int tx = tid & 7, ty = tid >> 3;        // ty 0..15, tx 0..7
    int mBase = blockIdx.x * 128;
    int nBase = blockIdx.y * 64;
    int m0 = ty * 8, n0 = tx * 8;

    int lrow = tid >> 2;                    // 0..31
    int lkc  = (tid & 3) * 4;

    ull acc[4][8];
    #pragma unroll
    for (int i = 0; i < 4; ++i)
        #pragma unroll
        for (int j = 0; j < 8; ++j) acc[i][j] = 0ull;

    float4 pa[4], pw[2];
    auto loadA = [&](int kt) {
        #pragma unroll
        for (int i = 0; i < 4; ++i) {
            int gr = mBase + lrow + i * 32;
            pa[i] = (gr < M) ? *(const float4*)&A[(size_t)gr * K + kt + lkc]
                             : make_float4(0.f, 0.f, 0.f, 0.f);
        }
    };
    auto loadW = [&](int kt) {
        #pragma unroll
        for (int i = 0; i < 2; ++i)
            pw[i] = *(const float4*)&W[(size_t)(nBase + lrow + i * 32) * K + kt + lkc];
    };

    loadA(0); loadW(0);

    for (int kt = 0; kt < K; kt += 16) {
        #pragma unroll
        for (int i = 0; i < 4; ++i) {
            int r = lrow + i * 32;
            As[lkc + 0][r] = pa[i].x; As[lkc + 1][r] = pa[i].y;
            As[lkc + 2][r] = pa[i].z; As[lkc + 3][r] = pa[i].w;
        }
        #pragma unroll
        for (int i = 0; i < 2; ++i) {
            int r = lrow + i * 32;
            Ws[lkc + 0][r] = pw[i].x; Ws[lkc + 1][r] = pw[i].y;
            Ws[lkc + 2][r] = pw[i].z; Ws[lkc + 3][r] = pw[i].w;
        }
        __syncthreads();

        if (kt + 16 < K) { loadA(kt + 16); loadW(kt + 16); }

        #pragma unroll
        for (int kk = 0; kk < 16; ++kk) {
            ulonglong2 a01 = *(const ulonglong2*)&As[kk][m0];
            ulonglong2 a23 = *(const ulonglong2*)&As[kk][m0 + 4];
            float4 b0 = *(const float4*)&Ws[kk][n0];
            float4 b1 = *(const float4*)&Ws[kk][n0 + 4];
            ull am[4] = {a01.x, a01.y, a23.x, a23.y};
            ull bd[8] = {dup2(b0.x), dup2(b0.y), dup2(b0.z), dup2(b0.w),
                         dup2(b1.x), dup2(b1.y), dup2(b1.z), dup2(b1.w)};
            #pragma unroll
            for (int mp = 0; mp < 4; ++mp)
                #pragma unroll
                for (int n = 0; n < 8; ++n) fma2(acc[mp][n], am[mp], bd[n]);
        }
        __syncthreads();
    }

    // attention-vector slices for this thread's 8 columns
    float a_s[8], a_d[8];
    {
        float4 t0 = *(const float4*)&asrc[nBase + n0];
        float4 t1 = *(const float4*)&asrc[nBase + n0 + 4];
        a_s[0]=t0.x; a_s[1]=t0.y; a_s[2]=t0.z; a_s[3]=t0.w;
        a_s[4]=t1.x; a_s[5]=t1.y; a_s[6]=t1.z; a_s[7]=t1.w;
        float4 u0 = *(const float4*)&adst[nBase + n0];
        float4 u1 = *(const float4*)&adst[nBase + n0 + 4];
        a_d[0]=u0.x; a_d[1]=u0.y; a_d[2]=u0.z; a_d[3]=u0.w;
        a_d[4]=u1.x; a_d[5]=u1.y; a_d[6]=u1.z; a_d[7]=u1.w;
    }

    #pragma unroll
    for (int mp = 0; mp < 4; ++mp) {
        float lo[8], hi[8];
        #pragma unroll
        for (int n = 0; n < 8; ++n) unpack2(acc[mp][n], lo[n], hi[n]);
        int r0 = mBase + m0 + 2 * mp;

        // partial score dots over this thread's 8 columns
        float sl = 0.f, dl = 0.f, sh = 0.f, dh = 0.f;
        #pragma unroll
        for (int n = 0; n < 8; ++n) {
            sl += lo[n] * a_s[n]; dl += lo[n] * a_d[n];
            sh += hi[n] * a_s[n]; dh += hi[n] * a_d[n];
        }
        #pragma unroll
        for (int off = 1; off < 8; off <<= 1) {
            sl += __shfl_xor_sync(0xffffffffu, sl, off);
            dl += __shfl_xor_sync(0xffffffffu, dl, off);
            sh += __shfl_xor_sync(0xffffffffu, sh, off);
            dh += __shfl_xor_sync(0xffffffffu, dh, off);
        }
        if (tx == 0) {
            if (r0 < M)     { atomicAdd(&ss[r0], sl);     atomicAdd(&ds[r0], dl); }
            if (r0 + 1 < M) { atomicAdd(&ss[r0 + 1], sh); atomicAdd(&ds[r0 + 1], dh); }
        }

        // bf16 store (8 cols = 16 B per row)
        if (r0 < M) {
            __nv_bfloat162 p0 = __floats2bfloat162_rn(lo[0], lo[1]);
            __nv_bfloat162 p1 = __floats2bfloat162_rn(lo[2], lo[3]);
            __nv_bfloat162 p2 = __floats2bfloat162_rn(lo[4], lo[5]);
            __nv_bfloat162 p3 = __floats2bfloat162_rn(lo[6], lo[7]);
            uint4 u;
            u.x = *(unsigned*)&p0; u.y = *(unsigned*)&p1;
            u.z = *(unsigned*)&p2; u.w = *(unsigned*)&p3;
            *(uint4*)&Cb[(size_t)r0 * Nout + nBase + n0] = u;
        }
        if (r0 + 1 < M) {
            __nv_bfloat162 p0 = __floats2bfloat162_rn(hi[0], hi[1]);
            __nv_bfloat162 p1 = __floats2bfloat162_rn(hi[2], hi[3]);
            __nv_bfloat162 p2 = __floats2bfloat162_rn(hi[4], hi[5]);
            __nv_bfloat162 p3 = __floats2bfloat162_rn(hi[6], hi[7]);
            uint4 u;
            u.x = *(unsigned*)&p0; u.y = *(unsigned*)&p1;
            u.z = *(unsigned*)&p2; u.w = *(unsigned*)&p3;
            *(uint4*)&Cb[(size_t)(r0 + 1) * Nout + nBase + n0] = u;
        }
    }
}

// ---------------- bf16 row loads ----------------
__device__ __forceinline__ float4 ldrow128(const __nv_bfloat16* base, int row, int lane) {
    uint2 u = ((const uint2*)(base + (size_t)row * 128))[lane];
    __nv_bfloat162 p0 = *(__nv_bfloat162*)&u.x;
    __nv_bfloat162 p1 = *(__nv_bfloat162*)&u.y;
    float2 f0 = __bfloat1622float2(p0);
    float2 f1 = __bfloat1622float2(p1);
    return make_float4(f0.x, f0.y, f1.x, f1.y);
}
__device__ __forceinline__ float2 ldrow64(const __nv_bfloat16* base, int row, int lane) {
    unsigned u = ((const unsigned*)(base + (size_t)row * 64))[lane];
    __nv_bfloat162 p = *(__nv_bfloat162*)&u;
    return __bfloat1622float2(p);
}

// ---------------- fused GAT aggregate + bias + ReLU + LayerNorm ----------------
template <int F>
__global__ void agg_kernel(const __nv_bfloat16* __restrict__ hbf,
                           const float* __restrict__ ss, const float* __restrict__ dsv,
                           const float* __restrict__ bias,
                           const float* __restrict__ gamma,
                           const float* __restrict__ beta,
                           float* __restrict__ out) {
    constexpr int VL = F / 32;
    int warp = (blockIdx.x * blockDim.x + threadIdx.x) >> 5;
    int lane = threadIdx.x & 31;
    if (warp >= NN) return;
    int n = warp;
    float dsn = dsv[n];
    int s0 = g_rowptr[n], s1 = g_rowptr[n + 1];

    float acc[VL];
    float w = __expf(lrelu(ss[n] + dsn));   // self loop
    float z = w;
    if constexpr (VL == 4) {
        float4 t = ldrow128(hbf, n, lane);
        acc[0] = w * t.x; acc[1] = w * t.y; acc[2] = w * t.z; acc[3] = w * t.w;
    } else {
        float2 t = ldrow64(hbf, n, lane);
        acc[0] = w * t.x; acc[1] = w * t.y;
    }

    int i = s0;
    for (; i + 2 <= s1; i += 2) {
        int sa = g_csrsrc[i];
        int sb = g_csrsrc[i + 1];
        float wa = __expf(lrelu(ss[sa] + dsn));
        float wb = __expf(lrelu(ss[sb] + dsn));
        z += wa + wb;
        if constexpr (VL == 4) {
            float4 ta = ldrow128(hbf, sa, lane);
            float4 tb = ldrow128(hbf, sb, lane);
            acc[0] += wa * ta.x + wb * tb.x;
            acc[1] += wa * ta.y + wb * tb.y;
            acc[2] += wa * ta.z + wb * tb.z;
            acc[3] += wa * ta.w + wb * tb.w;
        } else {
            float2 ta = ldrow64(hbf, sa, lane);
            float2 tb = ldrow64(hbf, sb, lane);
            acc[0] += wa * ta.x + wb * tb.x;
            acc[1] += wa * ta.y + wb * tb.y;
        }
    }
    if (i < s1) {
        int s = g_csrsrc[i];
        float ww = __expf(lrelu(ss[s] + dsn));
        z += ww;
        if constexpr (VL == 4) {
            float4 t = ldrow128(hbf, s, lane);
            acc[0] += ww * t.x; acc[1] += ww * t.y; acc[2] += ww * t.z; acc[3] += ww * t.w;
        } else {
            float2 t = ldrow64(hbf, s, lane);
            acc[0] += ww * t.x; acc[1] += ww * t.y;
        }
    }

    float inv = 1.f / z;
    float v[VL];
    float sum = 0.f;
    #pragma unroll
    for (int j = 0; j < VL; ++j) {
        v[j] = fmaxf(acc[j] * inv + bias[lane * VL + j], 0.f);  // bias + ReLU
        sum += v[j];
    }
    #pragma unroll
    for (int off = 16; off > 0; off >>= 1)
        sum += __shfl_xor_sync(0xffffffffu, sum, off);
    float mean = sum * (1.f / F);
    float vs = 0.f;
    #pragma unroll
    for (int j = 0; j < VL; ++j) {
        float d = v[j] - mean;
        vs += d * d;
    }
    #pragma unroll
    for (int off = 16; off > 0; off >>= 1)
        vs += __shfl_xor_sync(0xffffffffu, vs, off);
    float var = vs * (1.f / F);
    float r = rsqrtf(var + 1e-5f);
    if constexpr (VL == 4) {
        float4 gv = ((const float4*)gamma)[lane];
        float4 bv = ((const float4*)beta)[lane];
        float4 o;
        o.x = gv.x * (v[0] - mean) * r + bv.x;
        o.y = gv.y * (v[1] - mean) * r + bv.y;
        o.z = gv.z * (v[2] - mean) * r + bv.z;
        o.w = gv.w * (v[3] - mean) * r + bv.w;
        ((float4*)&out[(size_t)n * F])[lane] = o;
    } else {
        float2 gv = ((const float2*)gamma)[lane];
        float2 bv = ((const float2*)beta)[lane];
        float2 o;
        o.x = gv.x * (v[0] - mean) * r + bv.x;
        o.y = gv.y * (v[1] - mean) * r + bv.y;
        ((float2*)&out[(size_t)n * F])[lane] = o;
    }
}

// ---------------- global mean pool: run-length accumulate (batch is sorted) ----------------
__global__ void pool_kernel(const float* __restrict__ h, const int* __restrict__ batch) {
    int b = blockIdx.x;
    int f = threadIdx.x & 63;
    int q = threadIdx.x >> 6;
    int n0 = b * 64 + q * 16;
    float acc = 0.f;
    float cnt = 0.f;
    int curg = batch[n0];
    #pragma unroll 4
    for (int i = 0; i < 16; ++i) {
        int n = n0 + i;
        int g = batch[n];
        if (g != curg) {
            atomicAdd(&g_pool[curg * F2 + f], acc);
            if (f == 0) atomicAdd(&g_pcnt[curg], cnt);
            acc = 0.f; cnt = 0.f; curg = g;
        }
        acc += h[(size_t)n * F2 + f];
        cnt += 1.f;
    }
    atomicAdd(&g_pool[curg * F2 + f], acc);
    if (f == 0) atomicAdd(&g_pcnt[curg], cnt);
}

// ---------------- head: mean, 64x64 linear, 64->1 linear ----------------
__global__ void head_kernel(const float* __restrict__ Wl, const float* __restrict__ bl,
                            const float* __restrict__ Wc, const float* __restrict__ bc,
                            float* __restrict__ out) {
    __shared__ float p[F2];
    __shared__ float red[2];
    int g = blockIdx.x;
    int t = threadIdx.x;
    float c = g_pcnt[g];
    p[t] = g_pool[g * F2 + t] / fmaxf(c, 1.f);
    __syncthreads();
    float lin = bl[t];
    #pragma unroll 8
    for (int j = 0; j < F2; ++j) lin += p[j] * Wl[t * F2 + j];
    float part = lin * Wc[t];
    #pragma unroll
    for (int off = 16; off > 0; off >>= 1)
        part += __shfl_xor_sync(0xffffffffu, part, off);
    if ((t & 31) == 0) red[t >> 5] = part;
    __syncthreads();
    if (t == 0) out[g] = red[0] + red[1] + bc[0];
}

// ---------------- launch ----------------
extern "C" void kernel_launch(void* const* d_in, const int* in_sizes, int n_in,
                              void* d_out, int out_size) {
    const float* x    = (const float*)d_in[0];
    const int*   ei   = (const int*)d_in[1];
    const int*   batch= (const int*)d_in[2];
    const float* W1   = (const float*)d_in[3];
    const float* a1s  = (const float*)d_in[4];
    const float* a1d  = (const float*)d_in[5];
    const float* b1   = (const float*)d_in[6];
    const float* g1   = (const float*)d_in[7];
    const float* be1  = (const float*)d_in[8];
    const float* W2   = (const float*)d_in[9];
    const float* a2s  = (const float*)d_in[10];
    const float* a2d  = (const float*)d_in[11];
    const float* b2   = (const float*)d_in[12];
    const float* g2   = (const float*)d_in[13];
    const float* be2  = (const float*)d_in[14];
    const float* Wl   = (const float*)d_in[15];
    const float* bl   = (const float*)d_in[16];
    const float* Wc   = (const float*)d_in[17];
    const float* bc   = (const float*)d_in[18];
    float* out = (float*)d_out;

    const int* src = ei;
    const int* dst = ei + EE;

    __nv_bfloat16* phbf;
    float *phb, *pss1, *pds1, *pss2, *pds2;
    cudaGetSymbolAddress((void**)&phbf, g_hbf);
    cudaGetSymbolAddress((void**)&phb,  g_hb);
    cudaGetSymbolAddress((void**)&pss1, g_ss1);
    cudaGetSymbolAddress((void**)&pds1, g_ds1);
    cudaGetSymbolAddress((void**)&pss2, g_ss2);
    cudaGetSymbolAddress((void**)&pds2, g_ds2);

    const int NB = (NN + 255) / 256;   // 157

    // CSR build + zero scratch
    zero_kernel<<<NB, 256>>>();
    count_kernel<<<(EE + 255) / 256, 256>>>(dst);
    scan_kernel<<<NB, 256>>>();
    scatter_kernel<<<(EE + 255) / 256, 256>>>(src, dst);

    // layer 1 (GEMM writes bf16 h + scores)
    gemm_nt_f32x2<<<dim3((NN + 127) / 128, F1 / 64), 128>>>(
        x, W1, phbf, pss1, pds1, a1s, a1d, NN, F1, 128);
    agg_kernel<F1><<<(NN * 32 + 255) / 256, 256>>>(phbf, pss1, pds1, b1, g1, be1, phb);

    // layer 2
    gemm_nt_f32x2<<<dim3((NN + 127) / 128, F2 / 64), 128>>>(
        phb, W2, phbf, pss2, pds2, a2s, a2d, NN, F2, 128);
    agg_kernel<F2><<<(NN * 32 + 255) / 256, 256>>>(phbf, pss2, pds2, b2, g2, be2, phb);

    // pool + head
    pool_kernel<<<NN / 64, 256>>>(phb, batch);
    head_kernel<<<GG, F2>>>(Wl, bl, Wc, bc, out);
}

// round 5
// speedup vs baseline: 1.6331x; 1.0761x over previous
#include <cuda_runtime.h>
#include <cuda_bf16.h>

// Problem constants (fixed by the dataset)
#define NN 40000
#define EE 640000
#define GG 64
#define F1 128
#define F2 64

typedef unsigned long long ull;

// ---------------- scratch (no allocations allowed) ----------------
__device__ __nv_bfloat16 g_hbf[NN * F1];  // GEMM output (bf16) for gathers
__device__ float g_hb[NN * F1];           // agg+LN output (fp32, feeds next GEMM / pool)
__device__ float g_ss1[2 * NN], g_ds1[2 * NN];   // per-column-block partial scores (layer1)
__device__ float g_ss2[NN], g_ds2[NN];           // layer2 (single column block)
__device__ int   g_deg[NN];
__device__ int   g_cnt2[NN];
__device__ int   g_rowptr[NN + 1];
__device__ int   g_csrsrc[EE];
__device__ float g_pool[GG * F2];
__device__ float g_pcnt[GG];

__device__ __forceinline__ float lrelu(float x) { return x > 0.f ? x : 0.2f * x; }

__device__ __forceinline__ void fma2(ull& d, ull a, ull b) {
    asm("fma.rn.f32x2 %0, %1, %2, %0;" : "+l"(d) : "l"(a), "l"(b));
}
__device__ __forceinline__ ull dup2(float x) {
    ull r; asm("mov.b64 %0, {%1, %1};" : "=l"(r) : "f"(x)); return r;
}
__device__ __forceinline__ void unpack2(ull v, float& lo, float& hi) {
    asm("mov.b64 {%0, %1}, %2;" : "=f"(lo), "=f"(hi) : "l"(v));
}

// ---------------- zero scratch (CSR/pool side only) ----------------
__global__ void zero_kernel() {
    int i = blockIdx.x * blockDim.x + threadIdx.x;
    if (i < NN) { g_deg[i] = 0; g_cnt2[i] = 0; }
    if (i < GG * F2) g_pool[i] = 0.f;
    if (i < GG) g_pcnt[i] = 0.f;
}

// ---------------- CSR build ----------------
__global__ void count_kernel(const int* __restrict__ dst) {
    int i = blockIdx.x * blockDim.x + threadIdx.x;
    if (i < EE) atomicAdd(&g_deg[dst[i]], 1);
}

__device__ __forceinline__ int block_excl_scan(int v) {
    __shared__ int ws[8];
    int tid = threadIdx.x;
    int lane = tid & 31, wid = tid >> 5;
    int x = v;
    #pragma unroll
    for (int off = 1; off < 32; off <<= 1) {
        int y = __shfl_up_sync(0xffffffffu, x, off);
        if (lane >= off) x += y;
    }
    if (lane == 31) ws[wid] = x;
    __syncthreads();
    if (wid == 0) {
        int w = (lane < 8) ? ws[lane] : 0;
        #pragma unroll
        for (int off = 1; off < 8; off <<= 1) {
            int y = __shfl_up_sync(0xffffffffu, w, off);
            if (lane >= off) w += y;
        }
        if (lane < 8) ws[lane] = w;
    }
    __syncthreads();
    int add = (wid > 0) ? ws[wid - 1] : 0;
    return x - v + add;   // exclusive
}

// one-launch scan: each block recomputes its global offset itself
__global__ void scan_kernel() {
    __shared__ int red[8];
    __shared__ int s_off;
    int b = blockIdx.x, t = threadIdx.x;
    int lane = t & 31, wid = t >> 5;
    int lim = b * 256;
    int part = 0;
    for (int j = t; j < lim; j += 256) part += g_deg[j];
    #pragma unroll
    for (int off = 16; off > 0; off >>= 1) part += __shfl_xor_sync(0xffffffffu, part, off);
    if (lane == 0) red[wid] = part;
    __syncthreads();
    if (t == 0) {
        int s = 0;
        #pragma unroll
        for (int k = 0; k < 8; ++k) s += red[k];
        s_off = s;
    }
    __syncthreads();
    int off0 = s_off;
    int i = b * 256 + t;
    int v = (i < NN) ? g_deg[i] : 0;
    int e = block_excl_scan(v);
    if (i < NN) g_rowptr[i] = off0 + e;
    if (i == NN - 1) g_rowptr[NN] = off0 + e + v;
}

__global__ void scatter_kernel(const int* __restrict__ src, const int* __restrict__ dst) {
    int i = blockIdx.x * blockDim.x + threadIdx.x;
    if (i < EE) {
        int d = dst[i];
        int p = g_rowptr[d] + atomicAdd(&g_cnt2[d], 1);
        g_csrsrc[p] = src[i];
    }
}

// ---------------- packed-f32x2 GEMM with fused score epilogue ----------------
// C row stored as bf16; per-column-block partial score dots stored to
// ss[blockIdx.y*M + r] (plain stores, no atomics).
__global__ __launch_bounds__(128)
void gemm_nt_f32x2(const float* __restrict__ A, const float* __restrict__ W,
                   __nv_bfloat16* __restrict__ Cb,
                   float* __restrict__ ss, float* __restrict__ ds,
                   const float* __restrict__ asrc, const float* __restrict__ adst,
                   int M, int Nout, int K) {
    __shared__ float As[16][132];
    __shared__ float Ws[16][68];

    int tid = threadIdx.x;
    int tx = tid & 7, ty = tid >> 3;        // ty 0..15, tx 0..7
    int mBase = blockIdx.x * 128;
    int nBase = blockIdx.y * 64;
    int yoff = blockIdx.y * M;
    int m0 = ty * 8, n0 = tx * 8;

    int lrow = tid >> 2;                    // 0..31
    int lkc  = (tid & 3) * 4;

    ull acc[4][8];
    #pragma unroll
    for (int i = 0; i < 4; ++i)
        #pragma unroll
        for (int j = 0; j < 8; ++j) acc[i][j] = 0ull;

    float4 pa[4], pw[2];
    auto loadA = [&](int kt) {
        #pragma unroll
        for (int i = 0; i < 4; ++i) {
            int gr = mBase + lrow + i * 32;
            pa[i] = (gr < M) ? *(const float4*)&A[(size_t)gr * K + kt + lkc]
                             : make_float4(0.f, 0.f, 0.f, 0.f);
        }
    };
    auto loadW = [&](int kt) {
        #pragma unroll
        for (int i = 0; i < 2; ++i)
            pw[i] = *(const float4*)&W[(size_t)(nBase + lrow + i * 32) * K + kt + lkc];
    };

    loadA(0); loadW(0);

    for (int kt = 0; kt < K; kt += 16) {
        #pragma unroll
        for (int i = 0; i < 4; ++i) {
            int r = lrow + i * 32;
            As[lkc + 0][r] = pa[i].x; As[lkc + 1][r] = pa[i].y;
            As[lkc + 2][r] = pa[i].z; As[lkc + 3][r] = pa[i].w;
        }
        #pragma unroll
        for (int i = 0; i < 2; ++i) {
            int r = lrow + i * 32;
            Ws[lkc + 0][r] = pw[i].x; Ws[lkc + 1][r] = pw[i].y;
            Ws[lkc + 2][r] = pw[i].z; Ws[lkc + 3][r] = pw[i].w;
        }
        __syncthreads();

        if (kt + 16 < K) { loadA(kt + 16); loadW(kt + 16); }

        #pragma unroll
        for (int kk = 0; kk < 16; ++kk) {
            ulonglong2 a01 = *(const ulonglong2*)&As[kk][m0];
            ulonglong2 a23 = *(const ulonglong2*)&As[kk][m0 + 4];
            float4 b0 = *(const float4*)&Ws[kk][n0];
            float4 b1 = *(const float4*)&Ws[kk][n0 + 4];
            ull am[4] = {a01.x, a01.y, a23.x, a23.y};
            ull bd[8] = {dup2(b0.x), dup2(b0.y), dup2(b0.z), dup2(b0.w),
                         dup2(b1.x), dup2(b1.y), dup2(b1.z), dup2(b1.w)};
            #pragma unroll
            for (int mp = 0; mp < 4; ++mp)
                #pragma unroll
                for (int n = 0; n < 8; ++n) fma2(acc[mp][n], am[mp], bd[n]);
        }
        __syncthreads();
    }

    // attention-vector slices for this thread's 8 columns
    float a_s[8], a_d[8];
    {
        float4 t0 = *(const float4*)&asrc[nBase + n0];
        float4 t1 = *(const float4*)&asrc[nBase + n0 + 4];
        a_s[0]=t0.x; a_s[1]=t0.y; a_s[2]=t0.z; a_s[3]=t0.w;
        a_s[4]=t1.x; a_s[5]=t1.y; a_s[6]=t1.z; a_s[7]=t1.w;
        float4 u0 = *(const float4*)&adst[nBase + n0];
        float4 u1 = *(const float4*)&adst[nBase + n0 + 4];
        a_d[0]=u0.x; a_d[1]=u0.y; a_d[2]=u0.z; a_d[3]=u0.w;
        a_d[4]=u1.x; a_d[5]=u1.y; a_d[6]=u1.z; a_d[7]=u1.w;
    }

    #pragma unroll
    for (int mp = 0; mp < 4; ++mp) {
        float lo[8], hi[8];
        #pragma unroll
        for (int n = 0; n < 8; ++n) unpack2(acc[mp][n], lo[n], hi[n]);
        int r0 = mBase + m0 + 2 * mp;

        // partial score dots over this thread's 8 columns
        float sl = 0.f, dl = 0.f, sh = 0.f, dh = 0.f;
        #pragma unroll
        for (int n = 0; n < 8; ++n) {
            sl += lo[n] * a_s[n]; dl += lo[n] * a_d[n];
            sh += hi[n] * a_s[n]; dh += hi[n] * a_d[n];
        }
        #pragma unroll
        for (int off = 1; off < 8; off <<= 1) {
            sl += __shfl_xor_sync(0xffffffffu, sl, off);
            dl += __shfl_xor_sync(0xffffffffu, dl, off);
            sh += __shfl_xor_sync(0xffffffffu, sh, off);
            dh += __shfl_xor_sync(0xffffffffu, dh, off);
        }
        if (tx == 0) {
            if (r0 < M)     { ss[yoff + r0] = sl;     ds[yoff + r0] = dl; }
            if (r0 + 1 < M) { ss[yoff + r0 + 1] = sh; ds[yoff + r0 + 1] = dh; }
        }

        // bf16 store (8 cols = 16 B per row)
        if (r0 < M) {
            __nv_bfloat162 p0 = __floats2bfloat162_rn(lo[0], lo[1]);
            __nv_bfloat162 p1 = __floats2bfloat162_rn(lo[2], lo[3]);
            __nv_bfloat162 p2 = __floats2bfloat162_rn(lo[4], lo[5]);
            __nv_bfloat162 p3 = __floats2bfloat162_rn(lo[6], lo[7]);
            uint4 u;
            u.x = *(unsigned*)&p0; u.y = *(unsigned*)&p1;
            u.z = *(unsigned*)&p2; u.w = *(unsigned*)&p3;
            *(uint4*)&Cb[(size_t)r0 * Nout + nBase + n0] = u;
        }
        if (r0 + 1 < M) {
            __nv_bfloat162 p0 = __floats2bfloat162_rn(hi[0], hi[1]);
            __nv_bfloat162 p1 = __floats2bfloat162_rn(hi[2], hi[3]);
            __nv_bfloat162 p2 = __floats2bfloat162_rn(hi[4], hi[5]);
            __nv_bfloat162 p3 = __floats2bfloat162_rn(hi[6], hi[7]);
            uint4 u;
            u.x = *(unsigned*)&p0; u.y = *(unsigned*)&p1;
            u.z = *(unsigned*)&p2; u.w = *(unsigned*)&p3;
            *(uint4*)&Cb[(size_t)(r0 + 1) * Nout + nBase + n0] = u;
        }
    }
}

// ---------------- bf16 row loads ----------------
__device__ __forceinline__ float4 ldrow128(const __nv_bfloat16* base, int row, int lane) {
    uint2 u = ((const uint2*)(base + (size_t)row * 128))[lane];
    __nv_bfloat162 p0 = *(__nv_bfloat162*)&u.x;
    __nv_bfloat162 p1 = *(__nv_bfloat162*)&u.y;
    float2 f0 = __bfloat1622float2(p0);
    float2 f1 = __bfloat1622float2(p1);
    return make_float4(f0.x, f0.y, f1.x, f1.y);
}
__device__ __forceinline__ float2 ldrow64(const __nv_bfloat16* base, int row, int lane) {
    unsigned u = ((const unsigned*)(base + (size_t)row * 64))[lane];
    __nv_bfloat162 p = *(__nv_bfloat162*)&u;
    return __bfloat1622float2(p);
}

// ---------------- fused GAT aggregate + bias + ReLU + LayerNorm ----------------
// TWO: score arrays have 2 partial slices (layer1); else 1 (layer2).
template <int F, bool TWO>
__global__ void agg_kernel(const __nv_bfloat16* __restrict__ hbf,
                           const float* __restrict__ ssp, const float* __restrict__ dsp,
                           const float* __restrict__ bias,
                           const float* __restrict__ gamma,
                           const float* __restrict__ beta,
                           float* __restrict__ out) {
    constexpr int VL = F / 32;
    int warp = (blockIdx.x * blockDim.x + threadIdx.x) >> 5;
    int lane = threadIdx.x & 31;
    if (warp >= NN) return;
    int n = warp;
    float dsn = TWO ? (dsp[n] + dsp[n + NN]) : dsp[n];
    int s0 = g_rowptr[n], s1 = g_rowptr[n + 1];

    auto score = [&](int s) -> float {
        return TWO ? (ssp[s] + ssp[s + NN]) : ssp[s];
    };

    float acc[VL];
    float w = __expf(lrelu(score(n) + dsn));   // self loop
    float z = w;
    if constexpr (VL == 4) {
        float4 t = ldrow128(hbf, n, lane);
        acc[0] = w * t.x; acc[1] = w * t.y; acc[2] = w * t.z; acc[3] = w * t.w;
    } else {
        float2 t = ldrow64(hbf, n, lane);
        acc[0] = w * t.x; acc[1] = w * t.y;
    }

    int i = s0;
    for (; i + 2 <= s1; i += 2) {
        int sa = g_csrsrc[i];
        int sb = g_csrsrc[i + 1];
        float wa = __expf(lrelu(score(sa) + dsn));
        float wb = __expf(lrelu(score(sb) + dsn));
        z += wa + wb;
        if constexpr (VL == 4) {
            float4 ta = ldrow128(hbf, sa, lane);
            float4 tb = ldrow128(hbf, sb, lane);
            acc[0] += wa * ta.x + wb * tb.x;
            acc[1] += wa * ta.y + wb * tb.y;
            acc[2] += wa * ta.z + wb * tb.z;
            acc[3] += wa * ta.w + wb * tb.w;
        } else {
            float2 ta = ldrow64(hbf, sa, lane);
            float2 tb = ldrow64(hbf, sb, lane);
            acc[0] += wa * ta.x + wb * tb.x;
            acc[1] += wa * ta.y + wb * tb.y;
        }
    }
    if (i < s1) {
        int s = g_csrsrc[i];
        float ww = __expf(lrelu(score(s) + dsn));
        z += ww;
        if constexpr (VL == 4) {
            float4 t = ldrow128(hbf, s, lane);
            acc[0] += ww * t.x; acc[1] += ww * t.y; acc[2] += ww * t.z; acc[3] += ww * t.w;
        } else {
            float2 t = ldrow64(hbf, s, lane);
            acc[0] += ww * t.x; acc[1] += ww * t.y;
        }
    }

    float inv = 1.f / z;
    float v[VL];
    float sum = 0.f;
    #pragma unroll
    for (int j = 0; j < VL; ++j) {
        v[j] = fmaxf(acc[j] * inv + bias[lane * VL + j], 0.f);  // bias + ReLU
        sum += v[j];
    }
    #pragma unroll
    for (int off = 16; off > 0; off >>= 1)
        sum += __shfl_xor_sync(0xffffffffu, sum, off);
    float mean = sum * (1.f / F);
    float vs = 0.f;
    #pragma unroll
    for (int j = 0; j < VL; ++j) {
        float d = v[j] - mean;
        vs += d * d;
    }
    #pragma unroll
    for (int off = 16; off > 0; off >>= 1)
        vs += __shfl_xor_sync(0xffffffffu, vs, off);
    float var = vs * (1.f / F);
    float r = rsqrtf(var + 1e-5f);
    if constexpr (VL == 4) {
        float4 gv = ((const float4*)gamma)[lane];
        float4 bv = ((const float4*)beta)[lane];
        float4 o;
        o.x = gv.x * (v[0] - mean) * r + bv.x;
        o.y = gv.y * (v[1] - mean) * r + bv.y;
        o.z = gv.z * (v[2] - mean) * r + bv.z;
        o.w = gv.w * (v[3] - mean) * r + bv.w;
        ((float4*)&out[(size_t)n * F])[lane] = o;
    } else {
        float2 gv = ((const float2*)gamma)[lane];
        float2 bv = ((const float2*)beta)[lane];
        float2 o;
        o.x = gv.x * (v[0] - mean) * r + bv.x;
        o.y = gv.y * (v[1] - mean) * r + bv.y;
        ((float2*)&out[(size_t)n * F])[lane] = o;
    }
}

// ---------------- global mean pool: run-length accumulate (batch is sorted) ----------------
__global__ void pool_kernel(const float* __restrict__ h, const int* __restrict__ batch) {
    int b = blockIdx.x;
    int f = threadIdx.x & 63;
    int q = threadIdx.x >> 6;
    int n0 = b * 64 + q * 16;
    float acc = 0.f;
    float cnt = 0.f;
    int curg = batch[n0];
    #pragma unroll 4
    for (int i = 0; i < 16; ++i) {
        int n = n0 + i;
        int g = batch[n];
        if (g != curg) {
            atomicAdd(&g_pool[curg * F2 + f], acc);
            if (f == 0) atomicAdd(&g_pcnt[curg], cnt);
            acc = 0.f; cnt = 0.f; curg = g;
        }
        acc += h[(size_t)n * F2 + f];
        cnt += 1.f;
    }
    atomicAdd(&g_pool[curg * F2 + f], acc);
    if (f == 0) atomicAdd(&g_pcnt[curg], cnt);
}

// ---------------- head: mean, 64x64 linear, 64->1 linear ----------------
__global__ void head_kernel(const float* __restrict__ Wl, const float* __restrict__ bl,
                            const float* __restrict__ Wc, const float* __restrict__ bc,
                            float* __restrict__ out) {
    __shared__ float p[F2];
    __shared__ float red[2];
    int g = blockIdx.x;
    int t = threadIdx.x;
    float c = g_pcnt[g];
    p[t] = g_pool[g * F2 + t] / fmaxf(c, 1.f);
    __syncthreads();
    float lin = bl[t];
    #pragma unroll 8
    for (int j = 0; j < F2; ++j) lin += p[j] * Wl[t * F2 + j];
    float part = lin * Wc[t];
    #pragma unroll
    for (int off = 16; off > 0; off >>= 1)
        part += __shfl_xor_sync(0xffffffffu, part, off);
    if ((t & 31) == 0) red[t >> 5] = part;
    __syncthreads();
    if (t == 0) out[g] = red[0] + red[1] + bc[0];
}

// ---------------- launch ----------------
extern "C" void kernel_launch(void* const* d_in, const int* in_sizes, int n_in,
                              void* d_out, int out_size) {
    const float* x    = (const float*)d_in[0];
    const int*   ei   = (const int*)d_in[1];
    const int*   batch= (const int*)d_in[2];
    const float* W1   = (const float*)d_in[3];
    const float* a1s  = (const float*)d_in[4];
    const float* a1d  = (const float*)d_in[5];
    const float* b1   = (const float*)d_in[6];
    const float* g1   = (const float*)d_in[7];
    const float* be1  = (const float*)d_in[8];
    const float* W2   = (const float*)d_in[9];
    const float* a2s  = (const float*)d_in[10];
    const float* a2d  = (const float*)d_in[11];
    const float* b2   = (const float*)d_in[12];
    const float* g2   = (const float*)d_in[13];
    const float* be2  = (const float*)d_in[14];
    const float* Wl   = (const float*)d_in[15];
    const float* bl   = (const float*)d_in[16];
    const float* Wc   = (const float*)d_in[17];
    const float* bc   = (const float*)d_in[18];
    float* out = (float*)d_out;

    const int* src = ei;
    const int* dst = ei + EE;

    __nv_bfloat16* phbf;
    float *phb, *pss1, *pds1, *pss2, *pds2;
    cudaGetSymbolAddress((void**)&phbf, g_hbf);
    cudaGetSymbolAddress((void**)&phb,  g_hb);
    cudaGetSymbolAddress((void**)&pss1, g_ss1);
    cudaGetSymbolAddress((void**)&pds1, g_ds1);
    cudaGetSymbolAddress((void**)&pss2, g_ss2);
    cudaGetSymbolAddress((void**)&pds2, g_ds2);

    // side stream + fork/join events (created once; host-side objects only)
    static cudaStream_t s1 = nullptr;
    static cudaEvent_t eFork = nullptr, eJoin = nullptr;
    if (s1 == nullptr) {
        cudaStreamCreateWithFlags(&s1, cudaStreamNonBlocking);
        cudaEventCreateWithFlags(&eFork, cudaEventDisableTiming);
        cudaEventCreateWithFlags(&eJoin, cudaEventDisableTiming);
    }

    const int NB = (NN + 255) / 256;   // 157

    // fork: CSR build chain on s1, GEMM1 on main stream
    cudaEventRecord(eFork, 0);
    cudaStreamWaitEvent(s1, eFork, 0);

    zero_kernel<<<NB, 256, 0, s1>>>();
    count_kernel<<<(EE + 255) / 256, 256, 0, s1>>>(dst);
    scan_kernel<<<NB, 256, 0, s1>>>();
    scatter_kernel<<<(EE + 255) / 256, 256, 0, s1>>>(src, dst);
    cudaEventRecord(eJoin, s1);

    // layer 1 GEMM (independent of CSR)
    gemm_nt_f32x2<<<dim3((NN + 127) / 128, F1 / 64), 128>>>(
        x, W1, phbf, pss1, pds1, a1s, a1d, NN, F1, 128);

    // join: agg1 needs CSR + GEMM1
    cudaStreamWaitEvent(0, eJoin, 0);
    agg_kernel<F1, true><<<(NN * 32 + 255) / 256, 256>>>(phbf, pss1, pds1, b1, g1, be1, phb);

    // layer 2
    gemm_nt_f32x2<<<dim3((NN + 127) / 128, F2 / 64), 128>>>(
        phb, W2, phbf, pss2, pds2, a2s, a2d, NN, F2, 128);
    agg_kernel<F2, false><<<(NN * 32 + 255) / 256, 256>>>(phbf, pss2, pds2, b2, g2, be2, phb);

    // pool + head
    pool_kernel<<<NN / 64, 256>>>(phb, batch);
    head_kernel<<<GG, F2>>>(Wl, bl, Wc, bc, out);
}

// round 6
// speedup vs baseline: 1.6376x; 1.0028x over previous
#include <cuda_runtime.h>
#include <cuda_bf16.h>

// Problem constants (fixed by the dataset)
#define NN 40000
#define EE 640000
#define GG 64
#define F1 128
#define F2 64

typedef unsigned long long ull;

// ---------------- scratch (no allocations allowed) ----------------
__device__ __nv_bfloat16 g_hbf[NN * F1];  // GEMM output (bf16) for gathers
__device__ float g_hb[NN * F1];           // agg+LN output (fp32, feeds next GEMM / pool)
__device__ float g_ss1[2 * NN], g_ds1[2 * NN];   // per-column-block partial scores (layer1)
__device__ float g_ss2[NN], g_ds2[NN];           // layer2 (single column block)
__device__ int   g_deg[NN];               // zero at start of every run (see scatter)
__device__ int   g_rowptr[NN + 1];
__device__ int   g_rowptr2[NN];           // destructive cursor copy
__device__ int   g_csrsrc[EE];

__device__ __forceinline__ float lrelu(float x) { return x > 0.f ? x : 0.2f * x; }

__device__ __forceinline__ void fma2(ull& d, ull a, ull b) {
    asm("fma.rn.f32x2 %0, %1, %2, %0;" : "+l"(d) : "l"(a), "l"(b));
}
__device__ __forceinline__ ull dup2(float x) {
    ull r; asm("mov.b64 %0, {%1, %1};" : "=l"(r) : "f"(x)); return r;
}
__device__ __forceinline__ void unpack2(ull v, float& lo, float& hi) {
    asm("mov.b64 {%0, %1}, %2;" : "=f"(lo), "=f"(hi) : "l"(v));
}

// ---------------- CSR build ----------------
// 4 edges per thread (EE % 4 == 0)
__global__ void count_kernel(const int* __restrict__ dst) {
    int i = blockIdx.x * blockDim.x + threadIdx.x;
    if (i < EE / 4) {
        int4 d = ((const int4*)dst)[i];
        atomicAdd(&g_deg[d.x], 1);
        atomicAdd(&g_deg[d.y], 1);
        atomicAdd(&g_deg[d.z], 1);
        atomicAdd(&g_deg[d.w], 1);
    }
}

__device__ __forceinline__ int block_excl_scan(int v) {
    __shared__ int ws[8];
    int tid = threadIdx.x;
    int lane = tid & 31, wid = tid >> 5;
    int x = v;
    #pragma unroll
    for (int off = 1; off < 32; off <<= 1) {
        int y = __shfl_up_sync(0xffffffffu, x, off);
        if (lane >= off) x += y;
    }
    if (lane == 31) ws[wid] = x;
    __syncthreads();
    if (wid == 0) {
        int w = (lane < 8) ? ws[lane] : 0;
        #pragma unroll
        for (int off = 1; off < 8; off <<= 1) {
            int y = __shfl_up_sync(0xffffffffu, w, off);
            if (lane >= off) w += y;
        }
        if (lane < 8) ws[lane] = w;
    }
    __syncthreads();
    int add = (wid > 0) ? ws[wid - 1] : 0;
    return x - v + add;   // exclusive
}

// one-launch scan: each block recomputes its global offset itself
__global__ void scan_kernel() {
    __shared__ int red[8];
    __shared__ int s_off;
    int b = blockIdx.x, t = threadIdx.x;
    int lane = t & 31, wid = t >> 5;
    int lim = b * 256;
    int part = 0;
    for (int j = t; j < lim; j += 256) part += g_deg[j];
    #pragma unroll
    for (int off = 16; off > 0; off >>= 1) part += __shfl_xor_sync(0xffffffffu, part, off);
    if (lane == 0) red[wid] = part;
    __syncthreads();
    if (t == 0) {
        int s = 0;
        #pragma unroll
        for (int k = 0; k < 8; ++k) s += red[k];
        s_off = s;
    }
    __syncthreads();
    int off0 = s_off;
    int i = b * 256 + t;
    int v = (i < NN) ? g_deg[i] : 0;
    int e = block_excl_scan(v);
    if (i < NN) {
        g_rowptr[i]  = off0 + e;
        g_rowptr2[i] = off0 + e;   // destructive cursor copy
    }
    if (i == NN - 1) g_rowptr[NN] = off0 + e + v;
}

// single-atomic scatter (destructive rowptr2 cursor); also re-zeroes deg for the
// next replay (deg's last reader, scan, precedes this kernel).
__global__ void scatter_kernel(const int* __restrict__ src, const int* __restrict__ dst) {
    int i = blockIdx.x * blockDim.x + threadIdx.x;
    if (i < NN) g_deg[i] = 0;
    if (i < EE / 4) {
        int4 d = ((const int4*)dst)[i];
        int4 s = ((const int4*)src)[i];
        g_csrsrc[atomicAdd(&g_rowptr2[d.x], 1)] = s.x;
        g_csrsrc[atomicAdd(&g_rowptr2[d.y], 1)] = s.y;
        g_csrsrc[atomicAdd(&g_rowptr2[d.z], 1)] = s.z;
        g_csrsrc[atomicAdd(&g_rowptr2[d.w], 1)] = s.w;
    }
}

// ---------------- packed-f32x2 GEMM with fused score epilogue ----------------
__global__ __launch_bounds__(128)
void gemm_nt_f32x2(const float* __restrict__ A, const float* __restrict__ W,
                   __nv_bfloat16* __restrict__ Cb,
                   float* __restrict__ ss, float* __restrict__ ds,
                   const float* __restrict__ asrc, const float* __restrict__ adst,
                   int M, int Nout, int K) {
    __shared__ float As[16][132];
    __shared__ float Ws[16][68];

    int tid = threadIdx.x;
    int tx = tid & 7, ty = tid >> 3;        // ty 0..15, tx 0..7
    int mBase = blockIdx.x * 128;
    int nBase = blockIdx.y * 64;
    int yoff = blockIdx.y * M;
    int m0 = ty * 8, n0 = tx * 8;

    int lrow = tid >> 2;                    // 0..31
    int lkc  = (tid & 3) * 4;

    ull acc[4][8];
    #pragma unroll
    for (int i = 0; i < 4; ++i)
        #pragma unroll
        for (int j = 0; j < 8; ++j) acc[i][j] = 0ull;

    float4 pa[4], pw[2];
    auto loadA = [&](int kt) {
        #pragma unroll
        for (int i = 0; i < 4; ++i) {
            int gr = mBase + lrow + i * 32;
            pa[i] = (gr < M) ? *(const float4*)&A[(size_t)gr * K + kt + lkc]
                             : make_float4(0.f, 0.f, 0.f, 0.f);
        }
    };
    auto loadW = [&](int kt) {
        #pragma unroll
        for (int i = 0; i < 2; ++i)
            pw[i] = *(const float4*)&W[(size_t)(nBase + lrow + i * 32) * K + kt + lkc];
    };

    loadA(0); loadW(0);

    for (int kt = 0; kt < K; kt += 16) {
        #pragma unroll
        for (int i = 0; i < 4; ++i) {
            int r = lrow + i * 32;
            As[lkc + 0][r] = pa[i].x; As[lkc + 1][r] = pa[i].y;
            As[lkc + 2][r] = pa[i].z; As[lkc + 3][r] = pa[i].w;
        }
        #pragma unroll
        for (int i = 0; i < 2; ++i) {
            int r = lrow + i * 32;
            Ws[lkc + 0][r] = pw[i].x; Ws[lkc + 1][r] = pw[i].y;
            Ws[lkc + 2][r] = pw[i].z; Ws[lkc + 3][r] = pw[i].w;
        }
        __syncthreads();

        if (kt + 16 < K) { loadA(kt + 16); loadW(kt + 16); }

        #pragma unroll
        for (int kk = 0; kk < 16; ++kk) {
            ulonglong2 a01 = *(const ulonglong2*)&As[kk][m0];
            ulonglong2 a23 = *(const ulonglong2*)&As[kk][m0 + 4];
            float4 b0 = *(const float4*)&Ws[kk][n0];
            float4 b1 = *(const float4*)&Ws[kk][n0 + 4];
            ull am[4] = {a01.x, a01.y, a23.x, a23.y};
            ull bd[8] = {dup2(b0.x), dup2(b0.y), dup2(b0.z), dup2(b0.w),
                         dup2(b1.x), dup2(b1.y), dup2(b1.z), dup2(b1.w)};
            #pragma unroll
            for (int mp = 0; mp < 4; ++mp)
                #pragma unroll
                for (int n = 0; n < 8; ++n) fma2(acc[mp][n], am[mp], bd[n]);
        }
        __syncthreads();
    }

    float a_s[8], a_d[8];
    {
        float4 t0 = *(const float4*)&asrc[nBase + n0];
        float4 t1 = *(const float4*)&asrc[nBase + n0 + 4];
        a_s[0]=t0.x; a_s[1]=t0.y; a_s[2]=t0.z; a_s[3]=t0.w;
        a_s[4]=t1.x; a_s[5]=t1.y; a_s[6]=t1.z; a_s[7]=t1.w;
        float4 u0 = *(const float4*)&adst[nBase + n0];
        float4 u1 = *(const float4*)&adst[nBase + n0 + 4];
        a_d[0]=u0.x; a_d[1]=u0.y; a_d[2]=u0.z; a_d[3]=u0.w;
        a_d[4]=u1.x; a_d[5]=u1.y; a_d[6]=u1.z; a_d[7]=u1.w;
    }

    #pragma unroll
    for (int mp = 0; mp < 4; ++mp) {
        float lo[8], hi[8];
        #pragma unroll
        for (int n = 0; n < 8; ++n) unpack2(acc[mp][n], lo[n], hi[n]);
        int r0 = mBase + m0 + 2 * mp;

        float sl = 0.f, dl = 0.f, sh = 0.f, dh = 0.f;
        #pragma unroll
        for (int n = 0; n < 8; ++n) {
            sl += lo[n] * a_s[n]; dl += lo[n] * a_d[n];
            sh += hi[n] * a_s[n]; dh += hi[n] * a_d[n];
        }
        #pragma unroll
        for (int off = 1; off < 8; off <<= 1) {
            sl += __shfl_xor_sync(0xffffffffu, sl, off);
            dl += __shfl_xor_sync(0xffffffffu, dl, off);
            sh += __shfl_xor_sync(0xffffffffu, sh, off);
            dh += __shfl_xor_sync(0xffffffffu, dh, off);
        }
        if (tx == 0) {
            if (r0 < M)     { ss[yoff + r0] = sl;     ds[yoff + r0] = dl; }
            if (r0 + 1 < M) { ss[yoff + r0 + 1] = sh; ds[yoff + r0 + 1] = dh; }
        }

        if (r0 < M) {
            __nv_bfloat162 p0 = __floats2bfloat162_rn(lo[0], lo[1]);
            __nv_bfloat162 p1 = __floats2bfloat162_rn(lo[2], lo[3]);
            __nv_bfloat162 p2 = __floats2bfloat162_rn(lo[4], lo[5]);
            __nv_bfloat162 p3 = __floats2bfloat162_rn(lo[6], lo[7]);
            uint4 u;
            u.x = *(unsigned*)&p0; u.y = *(unsigned*)&p1;
            u.z = *(unsigned*)&p2; u.w = *(unsigned*)&p3;
            *(uint4*)&Cb[(size_t)r0 * Nout + nBase + n0] = u;
        }
        if (r0 + 1 < M) {
            __nv_bfloat162 p0 = __floats2bfloat162_rn(hi[0], hi[1]);
            __nv_bfloat162 p1 = __floats2bfloat162_rn(hi[2], hi[3]);
            __nv_bfloat162 p2 = __floats2bfloat162_rn(hi[4], hi[5]);
            __nv_bfloat162 p3 = __floats2bfloat162_rn(hi[6], hi[7]);
            uint4 u;
            u.x = *(unsigned*)&p0; u.y = *(unsigned*)&p1;
            u.z = *(unsigned*)&p2; u.w = *(unsigned*)&p3;
            *(uint4*)&Cb[(size_t)(r0 + 1) * Nout + nBase + n0] = u;
        }
    }
}

// ---------------- bf16 row loads ----------------
__device__ __forceinline__ float4 ldrow128(const __nv_bfloat16* base, int row, int lane) {
    uint2 u = ((const uint2*)(base + (size_t)row * 128))[lane];
    __nv_bfloat162 p0 = *(__nv_bfloat162*)&u.x;
    __nv_bfloat162 p1 = *(__nv_bfloat162*)&u.y;
    float2 f0 = __bfloat1622float2(p0);
    float2 f1 = __bfloat1622float2(p1);
    return make_float4(f0.x, f0.y, f1.x, f1.y);
}
__device__ __forceinline__ float2 ldrow64(const __nv_bfloat16* base, int row, int lane) {
    unsigned u = ((const unsigned*)(base + (size_t)row * 64))[lane];
    __nv_bfloat162 p = *(__nv_bfloat162*)&u;
    return __bfloat1622float2(p);
}

// ---------------- fused GAT aggregate + bias + ReLU + LayerNorm ----------------
template <int F, bool TWO>
__global__ void agg_kernel(const __nv_bfloat16* __restrict__ hbf,
                           const float* __restrict__ ssp, const float* __restrict__ dsp,
                           const float* __restrict__ bias,
                           const float* __restrict__ gamma,
                           const float* __restrict__ beta,
                           float* __restrict__ out) {
    constexpr int VL = F / 32;
    int warp = (blockIdx.x * blockDim.x + threadIdx.x) >> 5;
    int lane = threadIdx.x & 31;
    if (warp >= NN) return;
    int n = warp;
    float dsn = TWO ? (dsp[n] + dsp[n + NN]) : dsp[n];
    int s0 = g_rowptr[n], s1 = g_rowptr[n + 1];

    auto score = [&](int s) -> float {
        return TWO ? (ssp[s] + ssp[s + NN]) : ssp[s];
    };

    float acc[VL];
    float w = __expf(lrelu(score(n) + dsn));   // self loop
    float z = w;
    if constexpr (VL == 4) {
        float4 t = ldrow128(hbf, n, lane);
        acc[0] = w * t.x; acc[1] = w * t.y; acc[2] = w * t.z; acc[3] = w * t.w;
    } else {
        float2 t = ldrow64(hbf, n, lane);
        acc[0] = w * t.x; acc[1] = w * t.y;
    }

    int i = s0;
    // 4-edge unroll for gather MLP
    for (; i + 4 <= s1; i += 4) {
        int s[4];
        s[0] = g_csrsrc[i]; s[1] = g_csrsrc[i + 1];
        s[2] = g_csrsrc[i + 2]; s[3] = g_csrsrc[i + 3];
        float wv[4];
        #pragma unroll
        for (int k = 0; k < 4; ++k) { wv[k] = __expf(lrelu(score(s[k]) + dsn)); z += wv[k]; }
        if constexpr (VL == 4) {
            float4 t0 = ldrow128(hbf, s[0], lane);
            float4 t1 = ldrow128(hbf, s[1], lane);
            float4 t2 = ldrow128(hbf, s[2], lane);
            float4 t3 = ldrow128(hbf, s[3], lane);
            acc[0] += wv[0]*t0.x + wv[1]*t1.x + wv[2]*t2.x + wv[3]*t3.x;
            acc[1] += wv[0]*t0.y + wv[1]*t1.y + wv[2]*t2.y + wv[3]*t3.y;
            acc[2] += wv[0]*t0.z + wv[1]*t1.z + wv[2]*t2.z + wv[3]*t3.z;
            acc[3] += wv[0]*t0.w + wv[1]*t1.w + wv[2]*t2.w + wv[3]*t3.w;
        } else {
            float2 t0 = ldrow64(hbf, s[0], lane);
            float2 t1 = ldrow64(hbf, s[1], lane);
            float2 t2 = ldrow64(hbf, s[2], lane);
            float2 t3 = ldrow64(hbf, s[3], lane);
            acc[0] += wv[0]*t0.x + wv[1]*t1.x + wv[2]*t2.x + wv[3]*t3.x;
            acc[1] += wv[0]*t0.y + wv[1]*t1.y + wv[2]*t2.y + wv[3]*t3.y;
        }
    }
    for (; i < s1; ++i) {
        int s = g_csrsrc[i];
        float ww = __expf(lrelu(score(s) + dsn));
        z += ww;
        if constexpr (VL == 4) {
            float4 t = ldrow128(hbf, s, lane);
            acc[0] += ww * t.x; acc[1] += ww * t.y; acc[2] += ww * t.z; acc[3] += ww * t.w;
        } else {
            float2 t = ldrow64(hbf, s, lane);
            acc[0] += ww * t.x; acc[1] += ww * t.y;
        }
    }

    float inv = 1.f / z;
    float v[VL];
    float sum = 0.f;
    #pragma unroll
    for (int j = 0; j < VL; ++j) {
        v[j] = fmaxf(acc[j] * inv + bias[lane * VL + j], 0.f);  // bias + ReLU
        sum += v[j];
    }
    #pragma unroll
    for (int off = 16; off > 0; off >>= 1)
        sum += __shfl_xor_sync(0xffffffffu, sum, off);
    float mean = sum * (1.f / F);
    float vs = 0.f;
    #pragma unroll
    for (int j = 0; j < VL; ++j) {
        float d = v[j] - mean;
        vs += d * d;
    }
    #pragma unroll
    for (int off = 16; off > 0; off >>= 1)
        vs += __shfl_xor_sync(0xffffffffu, vs, off);
    float var = vs * (1.f / F);
    float r = rsqrtf(var + 1e-5f);
    if constexpr (VL == 4) {
        float4 gv = ((const float4*)gamma)[lane];
        float4 bv = ((const float4*)beta)[lane];
        float4 o;
        o.x = gv.x * (v[0] - mean) * r + bv.x;
        o.y = gv.y * (v[1] - mean) * r + bv.y;
        o.z = gv.z * (v[2] - mean) * r + bv.z;
        o.w = gv.w * (v[3] - mean) * r + bv.w;
        ((float4*)&out[(size_t)n * F])[lane] = o;
    } else {
        float2 gv = ((const float2*)gamma)[lane];
        float2 bv = ((const float2*)beta)[lane];
        float2 o;
        o.x = gv.x * (v[0] - mean) * r + bv.x;
        o.y = gv.y * (v[1] - mean) * r + bv.y;
        ((float2*)&out[(size_t)n * F])[lane] = o;
    }
}

// ---------------- fused pool + head: one block per graph (batch is sorted) ----------------
__global__ void poolhead_kernel(const float* __restrict__ h, const int* __restrict__ batch,
                                const float* __restrict__ Wl, const float* __restrict__ bl,
                                const float* __restrict__ Wc, const float* __restrict__ bc,
                                float* __restrict__ out) {
    __shared__ float psum[4][F2];
    __shared__ float p[F2];
    __shared__ int range[2];
    __shared__ float red[2];
    int g = blockIdx.x;
    int t = threadIdx.x;
    int f = t & 63, q = t >> 6;

    if (t < 2) {
        int val = g + t;          // lower_bound(batch, g) and lower_bound(batch, g+1)
        int lo = 0, hi = NN;
        while (lo < hi) {
            int mid = (lo + hi) >> 1;
            if (batch[mid] < val) lo = mid + 1; else hi = mid;
        }
        range[t] = lo;
    }
    __syncthreads();
    int lo = range[0], hi = range[1];

    float acc = 0.f;
    for (int n = lo + q; n < hi; n += 4) acc += h[(size_t)n * F2 + f];
    psum[q][f] = acc;
    __syncthreads();

    if (t < F2) {
        float cnt = (float)(hi - lo);
        float s = psum[0][t] + psum[1][t] + psum[2][t] + psum[3][t];
        p[t] = s / fmaxf(cnt, 1.f);
    }
    __syncthreads();

    if (t < F2) {
        float lin = bl[t];
        #pragma unroll 8
        for (int j = 0; j < F2; ++j) lin += p[j] * Wl[t * F2 + j];
        float part = lin * Wc[t];
        #pragma unroll
        for (int off = 16; off > 0; off >>= 1)
            part += __shfl_xor_sync(0xffffffffu, part, off);
        if ((t & 31) == 0) red[t >> 5] = part;
    }
    __syncthreads();
    if (t == 0) out[g] = red[0] + red[1] + bc[0];
}

// ---------------- launch ----------------
extern "C" void kernel_launch(void* const* d_in, const int* in_sizes, int n_in,
                              void* d_out, int out_size) {
    const float* x    = (const float*)d_in[0];
    const int*   ei   = (const int*)d_in[1];
    const int*   batch= (const int*)d_in[2];
    const float* W1   = (const float*)d_in[3];
    const float* a1s  = (const float*)d_in[4];
    const float* a1d  = (const float*)d_in[5];
    const float* b1   = (const float*)d_in[6];
    const float* g1   = (const float*)d_in[7];
    const float* be1  = (const float*)d_in[8];
    const float* W2   = (const float*)d_in[9];
    const float* a2s  = (const float*)d_in[10];
    const float* a2d  = (const float*)d_in[11];
    const float* b2   = (const float*)d_in[12];
    const float* g2   = (const float*)d_in[13];
    const float* be2  = (const float*)d_in[14];
    const float* Wl   = (const float*)d_in[15];
    const float* bl   = (const float*)d_in[16];
    const float* Wc   = (const float*)d_in[17];
    const float* bc   = (const float*)d_in[18];
    float* out = (float*)d_out;

    const int* src = ei;
    const int* dst = ei + EE;

    __nv_bfloat16* phbf;
    float *phb, *pss1, *pds1, *pss2, *pds2;
    cudaGetSymbolAddress((void**)&phbf, g_hbf);
    cudaGetSymbolAddress((void**)&phb,  g_hb);
    cudaGetSymbolAddress((void**)&pss1, g_ss1);
    cudaGetSymbolAddress((void**)&pds1, g_ds1);
    cudaGetSymbolAddress((void**)&pss2, g_ss2);
    cudaGetSymbolAddress((void**)&pds2, g_ds2);

    // side stream + fork/join events (created once; host-side objects only)
    static cudaStream_t s1 = nullptr;
    static cudaEvent_t eFork = nullptr, eJoin = nullptr;
    if (s1 == nullptr) {
        cudaStreamCreateWithFlags(&s1, cudaStreamNonBlocking);
        cudaEventCreateWithFlags(&eFork, cudaEventDisableTiming);
        cudaEventCreateWithFlags(&eJoin, cudaEventDisableTiming);
    }

    const int NB = (NN + 255) / 256;   // 157

    // fork: CSR build chain on s1, GEMM1 on main stream
    cudaEventRecord(eFork, 0);
    cudaStreamWaitEvent(s1, eFork, 0);

    count_kernel<<<(EE / 4 + 255) / 256, 256, 0, s1>>>(dst);
    scan_kernel<<<NB, 256, 0, s1>>>();
    scatter_kernel<<<(EE / 4 + 255) / 256, 256, 0, s1>>>(src, dst);
    cudaEventRecord(eJoin, s1);

    // layer 1 GEMM (independent of CSR)
    gemm_nt_f32x2<<<dim3((NN + 127) / 128, F1 / 64), 128>>>(
        x, W1, phbf, pss1, pds1, a1s, a1d, NN, F1, 128);

    // join: agg1 needs CSR + GEMM1
    cudaStreamWaitEvent(0, eJoin, 0);
    agg_kernel<F1, true><<<(NN * 32 + 255) / 256, 256>>>(phbf, pss1, pds1, b1, g1, be1, phb);

    // layer 2
    gemm_nt_f32x2<<<dim3((NN + 127) / 128, F2 / 64), 128>>>(
        phb, W2, phbf, pss2, pds2, a2s, a2d, NN, F2, 128);
    agg_kernel<F2, false><<<(NN * 32 + 255) / 256, 256>>>(phbf, pss2, pds2, b2, g2, be2, phb);

    // fused pool + head
    poolhead_kernel<<<GG, 256>>>(phb, batch, Wl, bl, Wc, bc, out);
}

// round 7
// speedup vs baseline: 1.6603x; 1.0138x over previous
#include <cuda_runtime.h>
#include <cuda_bf16.h>

// Problem constants (fixed by the dataset)
#define NN 40000
#define EE 640000
#define GG 64
#define F1 128
#define F2 64

typedef unsigned long long ull;

// ---------------- scratch (no allocations allowed) ----------------
__device__ __nv_bfloat16 g_hbf[NN * F1];  // GEMM output (bf16) for gathers
__device__ float g_hb[NN * F1];           // agg+LN output (fp32, feeds next GEMM / pool)
__device__ float g_ss1[2 * NN], g_ds1[2 * NN];   // per-column-block partial scores (layer1)
__device__ float g_ss2[NN], g_ds2[NN];           // layer2 (single column block)
__device__ int   g_deg[NN];               // zero at start of every run (see scatter)
__device__ int   g_rowptr[NN + 1];
__device__ int   g_rowptr2[NN];           // destructive cursor copy
__device__ int   g_csrsrc[EE];

__device__ __forceinline__ float lrelu(float x) { return x > 0.f ? x : 0.2f * x; }

__device__ __forceinline__ void fma2(ull& d, ull a, ull b) {
    asm("fma.rn.f32x2 %0, %1, %2, %0;" : "+l"(d) : "l"(a), "l"(b));
}
__device__ __forceinline__ ull dup2(float x) {
    ull r; asm("mov.b64 %0, {%1, %1};" : "=l"(r) : "f"(x)); return r;
}
__device__ __forceinline__ void unpack2(ull v, float& lo, float& hi) {
    asm("mov.b64 {%0, %1}, %2;" : "=f"(lo), "=f"(hi) : "l"(v));
}

// ---------------- CSR build ----------------
// 4 edges per thread (EE % 4 == 0)
__global__ void count_kernel(const int* __restrict__ dst) {
    int i = blockIdx.x * blockDim.x + threadIdx.x;
    if (i < EE / 4) {
        int4 d = ((const int4*)dst)[i];
        atomicAdd(&g_deg[d.x], 1);
        atomicAdd(&g_deg[d.y], 1);
        atomicAdd(&g_deg[d.z], 1);
        atomicAdd(&g_deg[d.w], 1);
    }
}

__device__ __forceinline__ int block_excl_scan(int v) {
    __shared__ int ws[8];
    int tid = threadIdx.x;
    int lane = tid & 31, wid = tid >> 5;
    int x = v;
    #pragma unroll
    for (int off = 1; off < 32; off <<= 1) {
        int y = __shfl_up_sync(0xffffffffu, x, off);
        if (lane >= off) x += y;
    }
    if (lane == 31) ws[wid] = x;
    __syncthreads();
    if (wid == 0) {
        int w = (lane < 8) ? ws[lane] : 0;
        #pragma unroll
        for (int off = 1; off < 8; off <<= 1) {
            int y = __shfl_up_sync(0xffffffffu, w, off);
            if (lane >= off) w += y;
        }
        if (lane < 8) ws[lane] = w;
    }
    __syncthreads();
    int add = (wid > 0) ? ws[wid - 1] : 0;
    return x - v + add;   // exclusive
}

// one-launch scan: each block recomputes its global offset itself
__global__ void scan_kernel() {
    __shared__ int red[8];
    __shared__ int s_off;
    int b = blockIdx.x, t = threadIdx.x;
    int lane = t & 31, wid = t >> 5;
    int lim = b * 256;
    int part = 0;
    for (int j = t; j < lim; j += 256) part += g_deg[j];
    #pragma unroll
    for (int off = 16; off > 0; off >>= 1) part += __shfl_xor_sync(0xffffffffu, part, off);
    if (lane == 0) red[wid] = part;
    __syncthreads();
    if (t == 0) {
        int s = 0;
        #pragma unroll
        for (int k = 0; k < 8; ++k) s += red[k];
        s_off = s;
    }
    __syncthreads();
    int off0 = s_off;
    int i = b * 256 + t;
    int v = (i < NN) ? g_deg[i] : 0;
    int e = block_excl_scan(v);
    if (i < NN) {
        g_rowptr[i]  = off0 + e;
        g_rowptr2[i] = off0 + e;   // destructive cursor copy
    }
    if (i == NN - 1) g_rowptr[NN] = off0 + e + v;
}

// single-atomic scatter (destructive rowptr2 cursor); also re-zeroes deg for the
// next replay (deg's last reader, scan, precedes this kernel).
__global__ void scatter_kernel(const int* __restrict__ src, const int* __restrict__ dst) {
    int i = blockIdx.x * blockDim.x + threadIdx.x;
    if (i < NN) g_deg[i] = 0;
    if (i < EE / 4) {
        int4 d = ((const int4*)dst)[i];
        int4 s = ((const int4*)src)[i];
        g_csrsrc[atomicAdd(&g_rowptr2[d.x], 1)] = s.x;
        g_csrsrc[atomicAdd(&g_rowptr2[d.y], 1)] = s.y;
        g_csrsrc[atomicAdd(&g_rowptr2[d.z], 1)] = s.z;
        g_csrsrc[atomicAdd(&g_rowptr2[d.w], 1)] = s.w;
    }
}

// ---------------- packed-f32x2 GEMM, smem double-buffered, high occupancy ----------------
// BM=128, BN=64, BK=16, 128 threads, per-thread 8m(4 f32x2 pairs) x 8n.
// Target 5 blocks/SM (<=102 regs): no register prefetch, 1 sync per K-tile.
__global__ __launch_bounds__(128, 5)
void gemm_nt_f32x2(const float* __restrict__ A, const float* __restrict__ W,
                   __nv_bfloat16* __restrict__ Cb,
                   float* __restrict__ ss, float* __restrict__ ds,
                   const float* __restrict__ asrc, const float* __restrict__ adst,
                   int M, int Nout, int K) {
    __shared__ float As[2][16][132];
    __shared__ float Ws[2][16][68];

    int tid = threadIdx.x;
    int tx = tid & 7, ty = tid >> 3;        // ty 0..15, tx 0..7
    int mBase = blockIdx.x * 128;
    int nBase = blockIdx.y * 64;
    int yoff = blockIdx.y * M;
    int m0 = ty * 8, n0 = tx * 8;

    int lrow = tid >> 2;                    // 0..31
    int lkc  = (tid & 3) * 4;

    ull acc[4][8];
    #pragma unroll
    for (int i = 0; i < 4; ++i)
        #pragma unroll
        for (int j = 0; j < 8; ++j) acc[i][j] = 0ull;

    auto fill = [&](int kt, int buf) {
        #pragma unroll
        for (int i = 0; i < 4; ++i) {
            int gr = mBase + lrow + i * 32;
            float4 v = (gr < M) ? *(const float4*)&A[(size_t)gr * K + kt + lkc]
                                : make_float4(0.f, 0.f, 0.f, 0.f);
            int r = lrow + i * 32;
            As[buf][lkc + 0][r] = v.x; As[buf][lkc + 1][r] = v.y;
            As[buf][lkc + 2][r] = v.z; As[buf][lkc + 3][r] = v.w;
        }
        #pragma unroll
        for (int i = 0; i < 2; ++i) {
            float4 v = *(const float4*)&W[(size_t)(nBase + lrow + i * 32) * K + kt + lkc];
            int r = lrow + i * 32;
            Ws[buf][lkc + 0][r] = v.x; Ws[buf][lkc + 1][r] = v.y;
            Ws[buf][lkc + 2][r] = v.z; Ws[buf][lkc + 3][r] = v.w;
        }
    };

    fill(0, 0);
    __syncthreads();

    int cur = 0;
    for (int kt = 0; kt < K; kt += 16) {
        if (kt + 16 < K) fill(kt + 16, cur ^ 1);
        #pragma unroll
        for (int kk = 0; kk < 16; ++kk) {
            ulonglong2 a01 = *(const ulonglong2*)&As[cur][kk][m0];
            ulonglong2 a23 = *(const ulonglong2*)&As[cur][kk][m0 + 4];
            ull am[4] = {a01.x, a01.y, a23.x, a23.y};
            float4 b0 = *(const float4*)&Ws[cur][kk][n0];
            float4 b1 = *(const float4*)&Ws[cur][kk][n0 + 4];
            float bf[8] = {b0.x, b0.y, b0.z, b0.w, b1.x, b1.y, b1.z, b1.w};
            #pragma unroll
            for (int n = 0; n < 8; ++n) {
                ull bd = dup2(bf[n]);
                #pragma unroll
                for (int mp = 0; mp < 4; ++mp) fma2(acc[mp][n], am[mp], bd);
            }
        }
        __syncthreads();
        cur ^= 1;
    }

    float a_s[8], a_d[8];
    {
        float4 t0 = *(const float4*)&asrc[nBase + n0];
        float4 t1 = *(const float4*)&asrc[nBase + n0 + 4];
        a_s[0]=t0.x; a_s[1]=t0.y; a_s[2]=t0.z; a_s[3]=t0.w;
        a_s[4]=t1.x; a_s[5]=t1.y; a_s[6]=t1.z; a_s[7]=t1.w;
        float4 u0 = *(const float4*)&adst[nBase + n0];
        float4 u1 = *(const float4*)&adst[nBase + n0 + 4];
        a_d[0]=u0.x; a_d[1]=u0.y; a_d[2]=u0.z; a_d[3]=u0.w;
        a_d[4]=u1.x; a_d[5]=u1.y; a_d[6]=u1.z; a_d[7]=u1.w;
    }

    #pragma unroll
    for (int mp = 0; mp < 4; ++mp) {
        float lo[8], hi[8];
        #pragma unroll
        for (int n = 0; n < 8; ++n) unpack2(acc[mp][n], lo[n], hi[n]);
        int r0 = mBase + m0 + 2 * mp;

        float sl = 0.f, dl = 0.f, sh = 0.f, dh = 0.f;
        #pragma unroll
        for (int n = 0; n < 8; ++n) {
            sl += lo[n] * a_s[n]; dl += lo[n] * a_d[n];
            sh += hi[n] * a_s[n]; dh += hi[n] * a_d[n];
        }
        #pragma unroll
        for (int off = 1; off < 8; off <<= 1) {
            sl += __shfl_xor_sync(0xffffffffu, sl, off);
            dl += __shfl_xor_sync(0xffffffffu, dl, off);
            sh += __shfl_xor_sync(0xffffffffu, sh, off);
            dh += __shfl_xor_sync(0xffffffffu, dh, off);
        }
        if (tx == 0) {
            if (r0 < M)     { ss[yoff + r0] = sl;     ds[yoff + r0] = dl; }
            if (r0 + 1 < M) { ss[yoff + r0 + 1] = sh; ds[yoff + r0 + 1] = dh; }
        }

        if (r0 < M) {
            __nv_bfloat162 p0 = __floats2bfloat162_rn(lo[0], lo[1]);
            __nv_bfloat162 p1 = __floats2bfloat162_rn(lo[2], lo[3]);
            __nv_bfloat162 p2 = __floats2bfloat162_rn(lo[4], lo[5]);
            __nv_bfloat162 p3 = __floats2bfloat162_rn(lo[6], lo[7]);
            uint4 u;
            u.x = *(unsigned*)&p0; u.y = *(unsigned*)&p1;
            u.z = *(unsigned*)&p2; u.w = *(unsigned*)&p3;
            *(uint4*)&Cb[(size_t)r0 * Nout + nBase + n0] = u;
        }
        if (r0 + 1 < M) {
            __nv_bfloat162 p0 = __floats2bfloat162_rn(hi[0], hi[1]);
            __nv_bfloat162 p1 = __floats2bfloat162_rn(hi[2], hi[3]);
            __nv_bfloat162 p2 = __floats2bfloat162_rn(hi[4], hi[5]);
            __nv_bfloat162 p3 = __floats2bfloat162_rn(hi[6], hi[7]);
            uint4 u;
            u.x = *(unsigned*)&p0; u.y = *(unsigned*)&p1;
            u.z = *(unsigned*)&p2; u.w = *(unsigned*)&p3;
            *(uint4*)&Cb[(size_t)(r0 + 1) * Nout + nBase + n0] = u;
        }
    }
}

// ---------------- bf16 row loads ----------------
__device__ __forceinline__ float4 ldrow128(const __nv_bfloat16* base, int row, int lane) {
    uint2 u = ((const uint2*)(base + (size_t)row * 128))[lane];
    __nv_bfloat162 p0 = *(__nv_bfloat162*)&u.x;
    __nv_bfloat162 p1 = *(__nv_bfloat162*)&u.y;
    float2 f0 = __bfloat1622float2(p0);
    float2 f1 = __bfloat1622float2(p1);
    return make_float4(f0.x, f0.y, f1.x, f1.y);
}
__device__ __forceinline__ float2 ldrow64(const __nv_bfloat16* base, int row, int lane) {
    unsigned u = ((const unsigned*)(base + (size_t)row * 64))[lane];
    __nv_bfloat162 p = *(__nv_bfloat162*)&u;
    return __bfloat1622float2(p);
}

// ---------------- fused GAT aggregate + bias + ReLU + LayerNorm ----------------
template <int F, bool TWO>
__global__ void agg_kernel(const __nv_bfloat16* __restrict__ hbf,
                           const float* __restrict__ ssp, const float* __restrict__ dsp,
                           const float* __restrict__ bias,
                           const float* __restrict__ gamma,
                           const float* __restrict__ beta,
                           float* __restrict__ out) {
    constexpr int VL = F / 32;
    int warp = (blockIdx.x * blockDim.x + threadIdx.x) >> 5;
    int lane = threadIdx.x & 31;
    if (warp >= NN) return;
    int n = warp;
    float dsn = TWO ? (dsp[n] + dsp[n + NN]) : dsp[n];
    int s0 = g_rowptr[n], s1 = g_rowptr[n + 1];

    auto score = [&](int s) -> float {
        return TWO ? (ssp[s] + ssp[s + NN]) : ssp[s];
    };

    float acc[VL];
    float w = __expf(lrelu(score(n) + dsn));   // self loop
    float z = w;
    if constexpr (VL == 4) {
        float4 t = ldrow128(hbf, n, lane);
        acc[0] = w * t.x; acc[1] = w * t.y; acc[2] = w * t.z; acc[3] = w * t.w;
    } else {
        float2 t = ldrow64(hbf, n, lane);
        acc[0] = w * t.x; acc[1] = w * t.y;
    }

    int i = s0;
    // 4-edge unroll for gather MLP
    for (; i + 4 <= s1; i += 4) {
        int s[4];
        s[0] = g_csrsrc[i]; s[1] = g_csrsrc[i + 1];
        s[2] = g_csrsrc[i + 2]; s[3] = g_csrsrc[i + 3];
        float wv[4];
        #pragma unroll
        for (int k = 0; k < 4; ++k) { wv[k] = __expf(lrelu(score(s[k]) + dsn)); z += wv[k]; }
        if constexpr (VL == 4) {
            float4 t0 = ldrow128(hbf, s[0], lane);
            float4 t1 = ldrow128(hbf, s[1], lane);
            float4 t2 = ldrow128(hbf, s[2], lane);
            float4 t3 = ldrow128(hbf, s[3], lane);
            acc[0] += wv[0]*t0.x + wv[1]*t1.x + wv[2]*t2.x + wv[3]*t3.x;
            acc[1] += wv[0]*t0.y + wv[1]*t1.y + wv[2]*t2.y + wv[3]*t3.y;
            acc[2] += wv[0]*t0.z + wv[1]*t1.z + wv[2]*t2.z + wv[3]*t3.z;
            acc[3] += wv[0]*t0.w + wv[1]*t1.w + wv[2]*t2.w + wv[3]*t3.w;
        } else {
            float2 t0 = ldrow64(hbf, s[0], lane);
            float2 t1 = ldrow64(hbf, s[1], lane);
            float2 t2 = ldrow64(hbf, s[2], lane);
            float2 t3 = ldrow64(hbf, s[3], lane);
            acc[0] += wv[0]*t0.x + wv[1]*t1.x + wv[2]*t2.x + wv[3]*t3.x;
            acc[1] += wv[0]*t0.y + wv[1]*t1.y + wv[2]*t2.y + wv[3]*t3.y;
        }
    }
    for (; i < s1; ++i) {
        int s = g_csrsrc[i];
        float ww = __expf(lrelu(score(s) + dsn));
        z += ww;
        if constexpr (VL == 4) {
            float4 t = ldrow128(hbf, s, lane);
            acc[0] += ww * t.x; acc[1] += ww * t.y; acc[2] += ww * t.z; acc[3] += ww * t.w;
        } else {
            float2 t = ldrow64(hbf, s, lane);
            acc[0] += ww * t.x; acc[1] += ww * t.y;
        }
    }

    float inv = 1.f / z;
    float v[VL];
    float sum = 0.f;
    #pragma unroll
    for (int j = 0; j < VL; ++j) {
        v[j] = fmaxf(acc[j] * inv + bias[lane * VL + j], 0.f);  // bias + ReLU
        sum += v[j];
    }
    #pragma unroll
    for (int off = 16; off > 0; off >>= 1)
        sum += __shfl_xor_sync(0xffffffffu, sum, off);
    float mean = sum * (1.f / F);
    float vs = 0.f;
    #pragma unroll
    for (int j = 0; j < VL; ++j) {
        float d = v[j] - mean;
        vs += d * d;
    }
    #pragma unroll
    for (int off = 16; off > 0; off >>= 1)
        vs += __shfl_xor_sync(0xffffffffu, vs, off);
    float var = vs * (1.f / F);
    float r = rsqrtf(var + 1e-5f);
    if constexpr (VL == 4) {
        float4 gv = ((const float4*)gamma)[lane];
        float4 bv = ((const float4*)beta)[lane];
        float4 o;
        o.x = gv.x * (v[0] - mean) * r + bv.x;
        o.y = gv.y * (v[1] - mean) * r + bv.y;
        o.z = gv.z * (v[2] - mean) * r + bv.z;
        o.w = gv.w * (v[3] - mean) * r + bv.w;
        ((float4*)&out[(size_t)n * F])[lane] = o;
    } else {
        float2 gv = ((const float2*)gamma)[lane];
        float2 bv = ((const float2*)beta)[lane];
        float2 o;
        o.x = gv.x * (v[0] - mean) * r + bv.x;
        o.y = gv.y * (v[1] - mean) * r + bv.y;
        ((float2*)&out[(size_t)n * F])[lane] = o;
    }
}

// ---------------- fused pool + head: one block per graph (batch is sorted) ----------------
__global__ void poolhead_kernel(const float* __restrict__ h, const int* __restrict__ batch,
                                const float* __restrict__ Wl, const float* __restrict__ bl,
                                const float* __restrict__ Wc, const float* __restrict__ bc,
                                float* __restrict__ out) {
    __shared__ float psum[4][F2];
    __shared__ float p[F2];
    __shared__ int range[2];
    __shared__ float red[2];
    int g = blockIdx.x;
    int t = threadIdx.x;
    int f = t & 63, q = t >> 6;

    if (t < 2) {
        int val = g + t;          // lower_bound(batch, g) and lower_bound(batch, g+1)
        int lo = 0, hi = NN;
        while (lo < hi) {
            int mid = (lo + hi) >> 1;
            if (batch[mid] < val) lo = mid + 1; else hi = mid;
        }
        range[t] = lo;
    }
    __syncthreads();
    int lo = range[0], hi = range[1];

    float acc = 0.f;
    for (int n = lo + q; n < hi; n += 4) acc += h[(size_t)n * F2 + f];
    psum[q][f] = acc;
    __syncthreads();

    if (t < F2) {
        float cnt = (float)(hi - lo);
        float s = psum[0][t] + psum[1][t] + psum[2][t] + psum[3][t];
        p[t] = s / fmaxf(cnt, 1.f);
    }
    __syncthreads();

    if (t < F2) {
        float lin = bl[t];
        #pragma unroll 8
        for (int j = 0; j < F2; ++j) lin += p[j] * Wl[t * F2 + j];
        float part = lin * Wc[t];
        #pragma unroll
        for (int off = 16; off > 0; off >>= 1)
            part += __shfl_xor_sync(0xffffffffu, part, off);
        if ((t & 31) == 0) red[t >> 5] = part;
    }
    __syncthreads();
    if (t == 0) out[g] = red[0] + red[1] + bc[0];
}

// ---------------- launch ----------------
extern "C" void kernel_launch(void* const* d_in, const int* in_sizes, int n_in,
                              void* d_out, int out_size) {
    const float* x    = (const float*)d_in[0];
    const int*   ei   = (const int*)d_in[1];
    const int*   batch= (const int*)d_in[2];
    const float* W1   = (const float*)d_in[3];
    const float* a1s  = (const float*)d_in[4];
    const float* a1d  = (const float*)d_in[5];
    const float* b1   = (const float*)d_in[6];
    const float* g1   = (const float*)d_in[7];
    const float* be1  = (const float*)d_in[8];
    const float* W2   = (const float*)d_in[9];
    const float* a2s  = (const float*)d_in[10];
    const float* a2d  = (const float*)d_in[11];
    const float* b2   = (const float*)d_in[12];
    const float* g2   = (const float*)d_in[13];
    const float* be2  = (const float*)d_in[14];
    const float* Wl   = (const float*)d_in[15];
    const float* bl   = (const float*)d_in[16];
    const float* Wc   = (const float*)d_in[17];
    const float* bc   = (const float*)d_in[18];
    float* out = (float*)d_out;

    const int* src = ei;
    const int* dst = ei + EE;

    __nv_bfloat16* phbf;
    float *phb, *pss1, *pds1, *pss2, *pds2;
    cudaGetSymbolAddress((void**)&phbf, g_hbf);
    cudaGetSymbolAddress((void**)&phb,  g_hb);
    cudaGetSymbolAddress((void**)&pss1, g_ss1);
    cudaGetSymbolAddress((void**)&pds1, g_ds1);
    cudaGetSymbolAddress((void**)&pss2, g_ss2);
    cudaGetSymbolAddress((void**)&pds2, g_ds2);

    // side stream + fork/join events (created once; host-side objects only)
    static cudaStream_t s1 = nullptr;
    static cudaEvent_t eFork = nullptr, eJoin = nullptr;
    if (s1 == nullptr) {
        cudaStreamCreateWithFlags(&s1, cudaStreamNonBlocking);
        cudaEventCreateWithFlags(&eFork, cudaEventDisableTiming);
        cudaEventCreateWithFlags(&eJoin, cudaEventDisableTiming);
    }

    const int NB = (NN + 255) / 256;   // 157

    // fork: CSR build chain on s1, GEMM1 on main stream
    cudaEventRecord(eFork, 0);
    cudaStreamWaitEvent(s1, eFork, 0);

    count_kernel<<<(EE / 4 + 255) / 256, 256, 0, s1>>>(dst);
    scan_kernel<<<NB, 256, 0, s1>>>();
    scatter_kernel<<<(EE / 4 + 255) / 256, 256, 0, s1>>>(src, dst);
    cudaEventRecord(eJoin, s1);

    // layer 1 GEMM (independent of CSR)
    gemm_nt_f32x2<<<dim3((NN + 127) / 128, F1 / 64), 128>>>(
        x, W1, phbf, pss1, pds1, a1s, a1d, NN, F1, 128);

    // join: agg1 needs CSR + GEMM1
    cudaStreamWaitEvent(0, eJoin, 0);
    agg_kernel<F1, true><<<(NN * 32 + 255) / 256, 256>>>(phbf, pss1, pds1, b1, g1, be1, phb);

    // layer 2
    gemm_nt_f32x2<<<dim3((NN + 127) / 128, F2 / 64), 128>>>(
        phb, W2, phbf, pss2, pds2, a2s, a2d, NN, F2, 128);
    agg_kernel<F2, false><<<(NN * 32 + 255) / 256, 256>>>(phbf, pss2, pds2, b2, g2, be2, phb);

    // fused pool + head
    poolhead_kernel<<<GG, 256>>>(phb, batch, Wl, bl, Wc, bc, out);
}

// round 8
// speedup vs baseline: 1.8067x; 1.0882x over previous
#include <cuda_runtime.h>
#include <cuda_bf16.h>

// Problem constants (fixed by the dataset)
#define NN 40000
#define EE 640000
#define GG 64
#define F1 128
#define F2 64

typedef unsigned long long ull;

// ---------------- scratch (no allocations allowed) ----------------
__device__ __nv_bfloat16 g_hbf[NN * F1];  // GEMM output (bf16) for gathers
__device__ float g_hb[NN * F1];           // agg+LN output (fp32, feeds next GEMM / pool)
__device__ float g_ss1[2 * NN], g_ds1[2 * NN];   // per-column-block partial scores (layer1)
__device__ float g_ss2[NN], g_ds2[NN];           // layer2 (single column block)
__device__ int   g_deg[NN];               // zero at start of every run (see scatter)
__device__ int   g_rowptr[NN + 1];
__device__ int   g_rowptr2[NN];           // destructive cursor copy
__device__ int   g_csrsrc[EE];

__device__ __forceinline__ float lrelu(float x) { return x > 0.f ? x : 0.2f * x; }

// ---------------- CSR build ----------------
// 4 edges per thread (EE % 4 == 0)
__global__ void count_kernel(const int* __restrict__ dst) {
    int i = blockIdx.x * blockDim.x + threadIdx.x;
    if (i < EE / 4) {
        int4 d = ((const int4*)dst)[i];
        atomicAdd(&g_deg[d.x], 1);
        atomicAdd(&g_deg[d.y], 1);
        atomicAdd(&g_deg[d.z], 1);
        atomicAdd(&g_deg[d.w], 1);
    }
}

__device__ __forceinline__ int block_excl_scan(int v) {
    __shared__ int ws[8];
    int tid = threadIdx.x;
    int lane = tid & 31, wid = tid >> 5;
    int x = v;
    #pragma unroll
    for (int off = 1; off < 32; off <<= 1) {
        int y = __shfl_up_sync(0xffffffffu, x, off);
        if (lane >= off) x += y;
    }
    if (lane == 31) ws[wid] = x;
    __syncthreads();
    if (wid == 0) {
        int w = (lane < 8) ? ws[lane] : 0;
        #pragma unroll
        for (int off = 1; off < 8; off <<= 1) {
            int y = __shfl_up_sync(0xffffffffu, w, off);
            if (lane >= off) w += y;
        }
        if (lane < 8) ws[lane] = w;
    }
    __syncthreads();
    int add = (wid > 0) ? ws[wid - 1] : 0;
    return x - v + add;   // exclusive
}

// one-launch scan: each block recomputes its global offset itself
__global__ void scan_kernel() {
    __shared__ int red[8];
    __shared__ int s_off;
    int b = blockIdx.x, t = threadIdx.x;
    int lane = t & 31, wid = t >> 5;
    int lim = b * 256;
    int part = 0;
    for (int j = t; j < lim; j += 256) part += g_deg[j];
    #pragma unroll
    for (int off = 16; off > 0; off >>= 1) part += __shfl_xor_sync(0xffffffffu, part, off);
    if (lane == 0) red[wid] = part;
    __syncthreads();
    if (t == 0) {
        int s = 0;
        #pragma unroll
        for (int k = 0; k < 8; ++k) s += red[k];
        s_off = s;
    }
    __syncthreads();
    int off0 = s_off;
    int i = b * 256 + t;
    int v = (i < NN) ? g_deg[i] : 0;
    int e = block_excl_scan(v);
    if (i < NN) {
        g_rowptr[i]  = off0 + e;
        g_rowptr2[i] = off0 + e;   // destructive cursor copy
    }
    if (i == NN - 1) g_rowptr[NN] = off0 + e + v;
}

// single-atomic scatter (destructive rowptr2 cursor); also re-zeroes deg.
__global__ void scatter_kernel(const int* __restrict__ src, const int* __restrict__ dst) {
    int i = blockIdx.x * blockDim.x + threadIdx.x;
    if (i < NN) g_deg[i] = 0;
    if (i < EE / 4) {
        int4 d = ((const int4*)dst)[i];
        int4 s = ((const int4*)src)[i];
        g_csrsrc[atomicAdd(&g_rowptr2[d.x], 1)] = s.x;
        g_csrsrc[atomicAdd(&g_rowptr2[d.y], 1)] = s.y;
        g_csrsrc[atomicAdd(&g_rowptr2[d.z], 1)] = s.z;
        g_csrsrc[atomicAdd(&g_rowptr2[d.w], 1)] = s.w;
    }
}

// ---------------- tf32 tensor-core GEMM with fused score epilogue ----------------
__device__ __forceinline__ unsigned f2tf32(float x) {
    unsigned r; asm("cvt.rna.tf32.f32 %0, %1;" : "=r"(r) : "f"(x)); return r;
}
__device__ __forceinline__ void mma_tf32(float* d, const unsigned* a, const unsigned* b) {
    asm volatile(
        "mma.sync.aligned.m16n8k8.row.col.f32.tf32.tf32.f32 "
        "{%0,%1,%2,%3}, {%4,%5,%6,%7}, {%8,%9}, {%0,%1,%2,%3};"
        : "+f"(d[0]), "+f"(d[1]), "+f"(d[2]), "+f"(d[3])
        : "r"(a[0]), "r"(a[1]), "r"(a[2]), "r"(a[3]), "r"(b[0]), "r"(b[1]));
}

// BM=128, BN=64, BK=16, 128 threads (4 warps). Warp w: rows [w*32, w*32+32).
// smem tiles stored in mma fragment order:
//  A frag (m16 x k8): fid = mtile*2+kstep (16 frags), word addr = fid*128 + lane*4 + slot
//    lane = (r16%8)*4 + (k8%4), slot = (r16>=8) + 2*(k8>=4)
//  B frag (n8 x k8):  fid = ntile*2+kstep (16 frags), word addr = fid*64 + lane*2 + slot
//    lane = n8*4 + (k8%4), slot = (k8>=4)
__global__ __launch_bounds__(128)
void gemm_tf32(const float* __restrict__ A, const float* __restrict__ W,
               __nv_bfloat16* __restrict__ Cb,
               float* __restrict__ ss, float* __restrict__ ds,
               const float* __restrict__ asrc, const float* __restrict__ adst,
               int M, int Nout, int K) {
    __shared__ unsigned As[2][16 * 128];
    __shared__ unsigned Ws[2][16 * 64];

    int tid = threadIdx.x;
    int w = tid >> 5, lane = tid & 31;
    int gid = lane >> 2, tig = lane & 3;
    int mBase = blockIdx.x * 128;
    int nBase = blockIdx.y * 64;
    int yoff = blockIdx.y * M;

    int lrow = tid >> 2;                    // 0..31
    int lkc  = (tid & 3) * 4;               // 0,4,8,12
    int kstepL = lkc >> 3;                  // 0/1
    int khL    = (lkc >> 2) & 1;            // k-half within k8

    float dacc[2][8][4];
    #pragma unroll
    for (int mt = 0; mt < 2; ++mt)
        #pragma unroll
        for (int nt = 0; nt < 8; ++nt)
            #pragma unroll
            for (int q = 0; q < 4; ++q) dacc[mt][nt][q] = 0.f;

    auto fill = [&](int kt, int buf) {
        #pragma unroll
        for (int i = 0; i < 4; ++i) {
            int r = lrow + i * 32;          // 0..127
            int gr = mBase + r;
            float4 v = (gr < M) ? *(const float4*)&A[(size_t)gr * K + kt + lkc]
                                : make_float4(0.f, 0.f, 0.f, 0.f);
            int mtile = r >> 4, r16 = r & 15;
            int laneBase = (r16 & 7) * 4;
            int slot = (r16 >> 3) + 2 * khL;
            int base = (mtile * 2 + kstepL) * 128 + slot;
            As[buf][base + (laneBase + 0) * 4] = f2tf32(v.x);
            As[buf][base + (laneBase + 1) * 4] = f2tf32(v.y);
            As[buf][base + (laneBase + 2) * 4] = f2tf32(v.z);
            As[buf][base + (laneBase + 3) * 4] = f2tf32(v.w);
        }
        #pragma unroll
        for (int i = 0; i < 2; ++i) {
            int wr = lrow + i * 32;         // 0..63
            float4 v = *(const float4*)&W[(size_t)(nBase + wr) * K + kt + lkc];
            int ntile = wr >> 3, n8 = wr & 7;
            int base = (ntile * 2 + kstepL) * 64 + khL;
            Ws[buf][base + (n8 * 4 + 0) * 2] = f2tf32(v.x);
            Ws[buf][base + (n8 * 4 + 1) * 2] = f2tf32(v.y);
            Ws[buf][base + (n8 * 4 + 2) * 2] = f2tf32(v.z);
            Ws[buf][base + (n8 * 4 + 3) * 2] = f2tf32(v.w);
        }
    };

    fill(0, 0);
    __syncthreads();

    int cur = 0;
    for (int kt = 0; kt < K; kt += 16) {
        if (kt + 16 < K) fill(kt + 16, cur ^ 1);
        #pragma unroll
        for (int kstep = 0; kstep < 2; ++kstep) {
            unsigned a[2][4], b[8][2];
            #pragma unroll
            for (int mt = 0; mt < 2; ++mt) {
                int fid = (2 * w + mt) * 2 + kstep;
                uint4 av = *(const uint4*)&As[cur][fid * 128 + lane * 4];
                a[mt][0] = av.x; a[mt][1] = av.y; a[mt][2] = av.z; a[mt][3] = av.w;
            }
            #pragma unroll
            for (int nt = 0; nt < 8; ++nt) {
                int fid = nt * 2 + kstep;
                uint2 bv = *(const uint2*)&Ws[cur][fid * 64 + lane * 2];
                b[nt][0] = bv.x; b[nt][1] = bv.y;
            }
            #pragma unroll
            for (int mt = 0; mt < 2; ++mt)
                #pragma unroll
                for (int nt = 0; nt < 8; ++nt)
                    mma_tf32(dacc[mt][nt], a[mt], b[nt]);
        }
        __syncthreads();
        cur ^= 1;
    }

    // attention vectors for this thread's columns (2 per ntile)
    float2 vs_[8], vd_[8];
    #pragma unroll
    for (int nt = 0; nt < 8; ++nt) {
        vs_[nt] = *(const float2*)&asrc[nBase + nt * 8 + 2 * tig];
        vd_[nt] = *(const float2*)&adst[nBase + nt * 8 + 2 * tig];
    }

    #pragma unroll
    for (int mt = 0; mt < 2; ++mt) {
        int r0 = mBase + w * 32 + mt * 16 + gid;   // row of d[0],d[1]
        int r1 = r0 + 8;                           // row of d[2],d[3]

        float sl = 0.f, dl = 0.f, sh = 0.f, dh = 0.f;
        #pragma unroll
        for (int nt = 0; nt < 8; ++nt) {
            sl += dacc[mt][nt][0] * vs_[nt].x + dacc[mt][nt][1] * vs_[nt].y;
            dl += dacc[mt][nt][0] * vd_[nt].x + dacc[mt][nt][1] * vd_[nt].y;
            sh += dacc[mt][nt][2] * vs_[nt].x + dacc[mt][nt][3] * vs_[nt].y;
            dh += dacc[mt][nt][2] * vd_[nt].x + dacc[mt][nt][3] * vd_[nt].y;
        }
        // reduce across the 4 lanes of the tig group
        #pragma unroll
        for (int off = 1; off < 4; off <<= 1) {
            sl += __shfl_xor_sync(0xffffffffu, sl, off);
            dl += __shfl_xor_sync(0xffffffffu, dl, off);
            sh += __shfl_xor_sync(0xffffffffu, sh, off);
            dh += __shfl_xor_sync(0xffffffffu, dh, off);
        }
        if (tig == 0) {
            if (r0 < M) { ss[yoff + r0] = sl; ds[yoff + r0] = dl; }
            if (r1 < M) { ss[yoff + r1] = sh; ds[yoff + r1] = dh; }
        }

        // bf16 stores: one bf16x2 (4B) per ntile per row
        #pragma unroll
        for (int nt = 0; nt < 8; ++nt) {
            int col = nBase + nt * 8 + 2 * tig;
            if (r0 < M) {
                __nv_bfloat162 p = __floats2bfloat162_rn(dacc[mt][nt][0], dacc[mt][nt][1]);
                *(unsigned*)&Cb[(size_t)r0 * Nout + col] = *(unsigned*)&p;
            }
            if (r1 < M) {
                __nv_bfloat162 p = __floats2bfloat162_rn(dacc[mt][nt][2], dacc[mt][nt][3]);
                *(unsigned*)&Cb[(size_t)r1 * Nout + col] = *(unsigned*)&p;
            }
        }
    }
}

// ---------------- bf16 row loads ----------------
__device__ __forceinline__ float4 ldrow128(const __nv_bfloat16* base, int row, int lane) {
    uint2 u = ((const uint2*)(base + (size_t)row * 128))[lane];
    __nv_bfloat162 p0 = *(__nv_bfloat162*)&u.x;
    __nv_bfloat162 p1 = *(__nv_bfloat162*)&u.y;
    float2 f0 = __bfloat1622float2(p0);
    float2 f1 = __bfloat1622float2(p1);
    return make_float4(f0.x, f0.y, f1.x, f1.y);
}
__device__ __forceinline__ float2 ldrow64(const __nv_bfloat16* base, int row, int lane) {
    unsigned u = ((const unsigned*)(base + (size_t)row * 64))[lane];
    __nv_bfloat162 p = *(__nv_bfloat162*)&u;
    return __bfloat1622float2(p);
}

// ---------------- fused GAT aggregate + bias + ReLU + LayerNorm ----------------
template <int F, bool TWO>
__global__ void agg_kernel(const __nv_bfloat16* __restrict__ hbf,
                           const float* __restrict__ ssp, const float* __restrict__ dsp,
                           const float* __restrict__ bias,
                           const float* __restrict__ gamma,
                           const float* __restrict__ beta,
                           float* __restrict__ out) {
    constexpr int VL = F / 32;
    int warp = (blockIdx.x * blockDim.x + threadIdx.x) >> 5;
    int lane = threadIdx.x & 31;
    if (warp >= NN) return;
    int n = warp;
    float dsn = TWO ? (dsp[n] + dsp[n + NN]) : dsp[n];
    int s0 = g_rowptr[n], s1 = g_rowptr[n + 1];

    auto score = [&](int s) -> float {
        return TWO ? (ssp[s] + ssp[s + NN]) : ssp[s];
    };

    float acc[VL];
    float w = __expf(lrelu(score(n) + dsn));   // self loop
    float z = w;
    if constexpr (VL == 4) {
        float4 t = ldrow128(hbf, n, lane);
        acc[0] = w * t.x; acc[1] = w * t.y; acc[2] = w * t.z; acc[3] = w * t.w;
    } else {
        float2 t = ldrow64(hbf, n, lane);
        acc[0] = w * t.x; acc[1] = w * t.y;
    }

    int i = s0;
    for (; i + 4 <= s1; i += 4) {
        int s[4];
        s[0] = g_csrsrc[i]; s[1] = g_csrsrc[i + 1];
        s[2] = g_csrsrc[i + 2]; s[3] = g_csrsrc[i + 3];
        float wv[4];
        #pragma unroll
        for (int k = 0; k < 4; ++k) { wv[k] = __expf(lrelu(score(s[k]) + dsn)); z += wv[k]; }
        if constexpr (VL == 4) {
            float4 t0 = ldrow128(hbf, s[0], lane);
            float4 t1 = ldrow128(hbf, s[1], lane);
            float4 t2 = ldrow128(hbf, s[2], lane);
            float4 t3 = ldrow128(hbf, s[3], lane);
            acc[0] += wv[0]*t0.x + wv[1]*t1.x + wv[2]*t2.x + wv[3]*t3.x;
            acc[1] += wv[0]*t0.y + wv[1]*t1.y + wv[2]*t2.y + wv[3]*t3.y;
            acc[2] += wv[0]*t0.z + wv[1]*t1.z + wv[2]*t2.z + wv[3]*t3.z;
            acc[3] += wv[0]*t0.w + wv[1]*t1.w + wv[2]*t2.w + wv[3]*t3.w;
        } else {
            float2 t0 = ldrow64(hbf, s[0], lane);
            float2 t1 = ldrow64(hbf, s[1], lane);
            float2 t2 = ldrow64(hbf, s[2], lane);
            float2 t3 = ldrow64(hbf, s[3], lane);
            acc[0] += wv[0]*t0.x + wv[1]*t1.x + wv[2]*t2.x + wv[3]*t3.x;
            acc[1] += wv[0]*t0.y + wv[1]*t1.y + wv[2]*t2.y + wv[3]*t3.y;
        }
    }
    for (; i < s1; ++i) {
        int s = g_csrsrc[i];
        float ww = __expf(lrelu(score(s) + dsn));
        z += ww;
        if constexpr (VL == 4) {
            float4 t = ldrow128(hbf, s, lane);
            acc[0] += ww * t.x; acc[1] += ww * t.y; acc[2] += ww * t.z; acc[3] += ww * t.w;
        } else {
            float2 t = ldrow64(hbf, s, lane);
            acc[0] += ww * t.x; acc[1] += ww * t.y;
        }
    }

    float inv = 1.f / z;
    float v[VL];
    float sum = 0.f;
    #pragma unroll
    for (int j = 0; j < VL; ++j) {
        v[j] = fmaxf(acc[j] * inv + bias[lane * VL + j], 0.f);  // bias + ReLU
        sum += v[j];
    }
    #pragma unroll
    for (int off = 16; off > 0; off >>= 1)
        sum += __shfl_xor_sync(0xffffffffu, sum, off);
    float mean = sum * (1.f / F);
    float vs = 0.f;
    #pragma unroll
    for (int j = 0; j < VL; ++j) {
        float d = v[j] - mean;
        vs += d * d;
    }
    #pragma unroll
    for (int off = 16; off > 0; off >>= 1)
        vs += __shfl_xor_sync(0xffffffffu, vs, off);
    float var = vs * (1.f / F);
    float r = rsqrtf(var + 1e-5f);
    if constexpr (VL == 4) {
        float4 gv = ((const float4*)gamma)[lane];
        float4 bv = ((const float4*)beta)[lane];
        float4 o;
        o.x = gv.x * (v[0] - mean) * r + bv.x;
        o.y = gv.y * (v[1] - mean) * r + bv.y;
        o.z = gv.z * (v[2] - mean) * r + bv.z;
        o.w = gv.w * (v[3] - mean) * r + bv.w;
        ((float4*)&out[(size_t)n * F])[lane] = o;
    } else {
        float2 gv = ((const float2*)gamma)[lane];
        float2 bv = ((const float2*)beta)[lane];
        float2 o;
        o.x = gv.x * (v[0] - mean) * r + bv.x;
        o.y = gv.y * (v[1] - mean) * r + bv.y;
        ((float2*)&out[(size_t)n * F])[lane] = o;
    }
}

// ---------------- fused pool + head: one block per graph (batch is sorted) ----------------
__global__ void poolhead_kernel(const float* __restrict__ h, const int* __restrict__ batch,
                                const float* __restrict__ Wl, const float* __restrict__ bl,
                                const float* __restrict__ Wc, const float* __restrict__ bc,
                                float* __restrict__ out) {
    __shared__ float psum[4][F2];
    __shared__ float p[F2];
    __shared__ int range[2];
    __shared__ float red[2];
    int g = blockIdx.x;
    int t = threadIdx.x;
    int f = t & 63, q = t >> 6;

    if (t < 2) {
        int val = g + t;
        int lo = 0, hi = NN;
        while (lo < hi) {
            int mid = (lo + hi) >> 1;
            if (batch[mid] < val) lo = mid + 1; else hi = mid;
        }
        range[t] = lo;
    }
    __syncthreads();
    int lo = range[0], hi = range[1];

    float acc = 0.f;
    for (int n = lo + q; n < hi; n += 4) acc += h[(size_t)n * F2 + f];
    psum[q][f] = acc;
    __syncthreads();

    if (t < F2) {
        float cnt = (float)(hi - lo);
        float s = psum[0][t] + psum[1][t] + psum[2][t] + psum[3][t];
        p[t] = s / fmaxf(cnt, 1.f);
    }
    __syncthreads();

    if (t < F2) {
        float lin = bl[t];
        #pragma unroll 8
        for (int j = 0; j < F2; ++j) lin += p[j] * Wl[t * F2 + j];
        float part = lin * Wc[t];
        #pragma unroll
        for (int off = 16; off > 0; off >>= 1)
            part += __shfl_xor_sync(0xffffffffu, part, off);
        if ((t & 31) == 0) red[t >> 5] = part;
    }
    __syncthreads();
    if (t == 0) out[g] = red[0] + red[1] + bc[0];
}

// ---------------- launch ----------------
extern "C" void kernel_launch(void* const* d_in, const int* in_sizes, int n_in,
                              void* d_out, int out_size) {
    const float* x    = (const float*)d_in[0];
    const int*   ei   = (const int*)d_in[1];
    const int*   batch= (const int*)d_in[2];
    const float* W1   = (const float*)d_in[3];
    const float* a1s  = (const float*)d_in[4];
    const float* a1d  = (const float*)d_in[5];
    const float* b1   = (const float*)d_in[6];
    const float* g1   = (const float*)d_in[7];
    const float* be1  = (const float*)d_in[8];
    const float* W2   = (const float*)d_in[9];
    const float* a2s  = (const float*)d_in[10];
    const float* a2d  = (const float*)d_in[11];
    const float* b2   = (const float*)d_in[12];
    const float* g2   = (const float*)d_in[13];
    const float* be2  = (const float*)d_in[14];
    const float* Wl   = (const float*)d_in[15];
    const float* bl   = (const float*)d_in[16];
    const float* Wc   = (const float*)d_in[17];
    const float* bc   = (const float*)d_in[18];
    float* out = (float*)d_out;

    const int* src = ei;
    const int* dst = ei + EE;

    __nv_bfloat16* phbf;
    float *phb, *pss1, *pds1, *pss2, *pds2;
    cudaGetSymbolAddress((void**)&phbf, g_hbf);
    cudaGetSymbolAddress((void**)&phb,  g_hb);
    cudaGetSymbolAddress((void**)&pss1, g_ss1);
    cudaGetSymbolAddress((void**)&pds1, g_ds1);
    cudaGetSymbolAddress((void**)&pss2, g_ss2);
    cudaGetSymbolAddress((void**)&pds2, g_ds2);

    // side stream + fork/join events (created once; host-side objects only)
    static cudaStream_t s1 = nullptr;
    static cudaEvent_t eFork = nullptr, eJoin = nullptr;
    if (s1 == nullptr) {
        cudaStreamCreateWithFlags(&s1, cudaStreamNonBlocking);
        cudaEventCreateWithFlags(&eFork, cudaEventDisableTiming);
        cudaEventCreateWithFlags(&eJoin, cudaEventDisableTiming);
    }

    const int NB = (NN + 255) / 256;   // 157

    // fork: CSR build chain on s1, GEMM1 on main stream
    cudaEventRecord(eFork, 0);
    cudaStreamWaitEvent(s1, eFork, 0);

    count_kernel<<<(EE / 4 + 255) / 256, 256, 0, s1>>>(dst);
    scan_kernel<<<NB, 256, 0, s1>>>();
    scatter_kernel<<<(EE / 4 + 255) / 256, 256, 0, s1>>>(src, dst);
    cudaEventRecord(eJoin, s1);

    // layer 1 GEMM (independent of CSR)
    gemm_tf32<<<dim3((NN + 127) / 128, F1 / 64), 128>>>(
        x, W1, phbf, pss1, pds1, a1s, a1d, NN, F1, 128);

    // join: agg1 needs CSR + GEMM1
    cudaStreamWaitEvent(0, eJoin, 0);
    agg_kernel<F1, true><<<(NN * 32 + 255) / 256, 256>>>(phbf, pss1, pds1, b1, g1, be1, phb);

    // layer 2
    gemm_tf32<<<dim3((NN + 127) / 128, F2 / 64), 128>>>(
        phb, W2, phbf, pss2, pds2, a2s, a2d, NN, F2, 128);
    agg_kernel<F2, false><<<(NN * 32 + 255) / 256, 256>>>(phbf, pss2, pds2, b2, g2, be2, phb);

    // fused pool + head
    poolhead_kernel<<<GG, 256>>>(phb, batch, Wl, bl, Wc, bc, out);
}

// round 9
// speedup vs baseline: 1.8917x; 1.0470x over previous
#include <cuda_runtime.h>
#include <cuda_bf16.h>

// Problem constants (fixed by the dataset)
#define NN 40000
#define EE 640000
#define GG 64
#define F1 128
#define F2 64

typedef unsigned long long ull;

// ---------------- scratch (no allocations allowed) ----------------
__device__ __nv_bfloat16 g_hbf[NN * F1];  // GEMM output (bf16) for gathers
__device__ float g_hb[NN * F1];           // agg+LN output (fp32, feeds next GEMM / pool)
__device__ float g_ss1[2 * NN], g_ds1[2 * NN];   // per-column-block partial scores (layer1)
__device__ float g_ss2[NN], g_ds2[NN];           // layer2 (single column block)
__device__ int   g_deg[NN];               // zero at start of every run (see scatter)
__device__ int   g_rowptr[NN + 1];
__device__ int   g_rowptr2[NN];           // destructive cursor copy
__device__ int   g_csrsrc[EE];

__device__ __forceinline__ float lrelu(float x) { return x > 0.f ? x : 0.2f * x; }

// ---------------- CSR build ----------------
// 4 edges per thread (EE % 4 == 0)
__global__ void count_kernel(const int* __restrict__ dst) {
    int i = blockIdx.x * blockDim.x + threadIdx.x;
    if (i < EE / 4) {
        int4 d = ((const int4*)dst)[i];
        atomicAdd(&g_deg[d.x], 1);
        atomicAdd(&g_deg[d.y], 1);
        atomicAdd(&g_deg[d.z], 1);
        atomicAdd(&g_deg[d.w], 1);
    }
}

__device__ __forceinline__ int block_excl_scan(int v) {
    __shared__ int ws[8];
    int tid = threadIdx.x;
    int lane = tid & 31, wid = tid >> 5;
    int x = v;
    #pragma unroll
    for (int off = 1; off < 32; off <<= 1) {
        int y = __shfl_up_sync(0xffffffffu, x, off);
        if (lane >= off) x += y;
    }
    if (lane == 31) ws[wid] = x;
    __syncthreads();
    if (wid == 0) {
        int w = (lane < 8) ? ws[lane] : 0;
        #pragma unroll
        for (int off = 1; off < 8; off <<= 1) {
            int y = __shfl_up_sync(0xffffffffu, w, off);
            if (lane >= off) w += y;
        }
        if (lane < 8) ws[lane] = w;
    }
    __syncthreads();
    int add = (wid > 0) ? ws[wid - 1] : 0;
    return x - v + add;   // exclusive
}

// one-launch scan: each block recomputes its global offset itself
__global__ void scan_kernel() {
    __shared__ int red[8];
    __shared__ int s_off;
    int b = blockIdx.x, t = threadIdx.x;
    int lane = t & 31, wid = t >> 5;
    int lim = b * 256;
    int part = 0;
    for (int j = t; j < lim; j += 256) part += g_deg[j];
    #pragma unroll
    for (int off = 16; off > 0; off >>= 1) part += __shfl_xor_sync(0xffffffffu, part, off);
    if (lane == 0) red[wid] = part;
    __syncthreads();
    if (t == 0) {
        int s = 0;
        #pragma unroll
        for (int k = 0; k < 8; ++k) s += red[k];
        s_off = s;
    }
    __syncthreads();
    int off0 = s_off;
    int i = b * 256 + t;
    int v = (i < NN) ? g_deg[i] : 0;
    int e = block_excl_scan(v);
    if (i < NN) {
        g_rowptr[i]  = off0 + e;
        g_rowptr2[i] = off0 + e;   // destructive cursor copy
    }
    if (i == NN - 1) g_rowptr[NN] = off0 + e + v;
}

// single-atomic scatter (destructive rowptr2 cursor); also re-zeroes deg.
__global__ void scatter_kernel(const int* __restrict__ src, const int* __restrict__ dst) {
    int i = blockIdx.x * blockDim.x + threadIdx.x;
    if (i < NN) g_deg[i] = 0;
    if (i < EE / 4) {
        int4 d = ((const int4*)dst)[i];
        int4 s = ((const int4*)src)[i];
        g_csrsrc[atomicAdd(&g_rowptr2[d.x], 1)] = s.x;
        g_csrsrc[atomicAdd(&g_rowptr2[d.y], 1)] = s.y;
        g_csrsrc[atomicAdd(&g_rowptr2[d.z], 1)] = s.z;
        g_csrsrc[atomicAdd(&g_rowptr2[d.w], 1)] = s.w;
    }
}

// ---------------- tf32 tensor-core GEMM with fused score epilogue ----------------
__device__ __forceinline__ unsigned f2tf32(float x) {
    unsigned r; asm("cvt.rna.tf32.f32 %0, %1;" : "=r"(r) : "f"(x)); return r;
}
__device__ __forceinline__ void mma_tf32(float* d, const unsigned* a, const unsigned* b) {
    asm volatile(
        "mma.sync.aligned.m16n8k8.row.col.f32.tf32.tf32.f32 "
        "{%0,%1,%2,%3}, {%4,%5,%6,%7}, {%8,%9}, {%0,%1,%2,%3};"
        : "+f"(d[0]), "+f"(d[1]), "+f"(d[2]), "+f"(d[3])
        : "r"(a[0]), "r"(a[1]), "r"(a[2]), "r"(a[3]), "r"(b[0]), "r"(b[1]));
}

// BM=128, BN=64, BK=16, 128 threads (4 warps). Warp w: rows [w*32, w*32+32).
// smem tiles in mma fragment order, word layout [slot][lane] per fragment:
//  A frag (m16 x k8): fid = mtile*2+kstep (16 frags), word = fid*128 + slot*32 + lane
//    lane = (r16%8)*4 + (k8%4), slot = (r16>=8) + 2*(k8>=4)
//    -> fill: one STS.128 per thread per row-chunk (conflict-free),
//       mma load: 4x LDS.32 stride-32-words (conflict-free)
//  B frag (n8 x k8):  fid = ntile*2+kstep (16 frags), word = fid*64 + slot*32 + lane
//    lane = n8*4 + (k8%4), slot = (k8>=4)
__global__ __launch_bounds__(128)
void gemm_tf32(const float* __restrict__ A, const float* __restrict__ W,
               __nv_bfloat16* __restrict__ Cb,
               float* __restrict__ ss, float* __restrict__ ds,
               const float* __restrict__ asrc, const float* __restrict__ adst,
               int M, int Nout, int K) {
    __shared__ unsigned As[2][16 * 128];
    __shared__ unsigned Ws[2][16 * 64];

    int tid = threadIdx.x;
    int w = tid >> 5, lane = tid & 31;
    int gid = lane >> 2, tig = lane & 3;
    int mBase = blockIdx.x * 128;
    int nBase = blockIdx.y * 64;
    int yoff = blockIdx.y * M;

    int lrow = tid >> 2;                    // 0..31
    int lkc  = (tid & 3) * 4;               // 0,4,8,12
    int kstepL = lkc >> 3;                  // 0/1
    int khL    = (lkc >> 2) & 1;            // k-half within k8

    float dacc[2][8][4];
    #pragma unroll
    for (int mt = 0; mt < 2; ++mt)
        #pragma unroll
        for (int nt = 0; nt < 8; ++nt)
            #pragma unroll
            for (int q = 0; q < 4; ++q) dacc[mt][nt][q] = 0.f;

    auto fill = [&](int kt, int buf) {
        #pragma unroll
        for (int i = 0; i < 4; ++i) {
            int r = lrow + i * 32;          // 0..127
            int gr = mBase + r;
            float4 v = (gr < M) ? *(const float4*)&A[(size_t)gr * K + kt + lkc]
                                : make_float4(0.f, 0.f, 0.f, 0.f);
            int mtile = r >> 4, r16 = r & 15;
            int slot = (r16 >> 3) + 2 * khL;
            int addr = (mtile * 2 + kstepL) * 128 + slot * 32 + (r16 & 7) * 4;
            uint4 u;
            u.x = f2tf32(v.x); u.y = f2tf32(v.y); u.z = f2tf32(v.z); u.w = f2tf32(v.w);
            *(uint4*)&As[buf][addr] = u;
        }
        #pragma unroll
        for (int i = 0; i < 2; ++i) {
            int wr = lrow + i * 32;         // 0..63
            float4 v = *(const float4*)&W[(size_t)(nBase + wr) * K + kt + lkc];
            int ntile = wr >> 3, n8 = wr & 7;
            int addr = (ntile * 2 + kstepL) * 64 + khL * 32 + n8 * 4;
            uint4 u;
            u.x = f2tf32(v.x); u.y = f2tf32(v.y); u.z = f2tf32(v.z); u.w = f2tf32(v.w);
            *(uint4*)&Ws[buf][addr] = u;
        }
    };

    fill(0, 0);
    __syncthreads();

    int cur = 0;
    for (int kt = 0; kt < K; kt += 16) {
        if (kt + 16 < K) fill(kt + 16, cur ^ 1);
        #pragma unroll
        for (int kstep = 0; kstep < 2; ++kstep) {
            unsigned a[2][4], b[8][2];
            #pragma unroll
            for (int mt = 0; mt < 2; ++mt) {
                int base = ((2 * w + mt) * 2 + kstep) * 128 + lane;
                a[mt][0] = As[cur][base];
                a[mt][1] = As[cur][base + 32];
                a[mt][2] = As[cur][base + 64];
                a[mt][3] = As[cur][base + 96];
            }
            #pragma unroll
            for (int nt = 0; nt < 8; ++nt) {
                int base = (nt * 2 + kstep) * 64 + lane;
                b[nt][0] = Ws[cur][base];
                b[nt][1] = Ws[cur][base + 32];
            }
            #pragma unroll
            for (int mt = 0; mt < 2; ++mt)
                #pragma unroll
                for (int nt = 0; nt < 8; ++nt)
                    mma_tf32(dacc[mt][nt], a[mt], b[nt]);
        }
        __syncthreads();
        cur ^= 1;
    }

    // attention vectors for this thread's columns (2 per ntile)
    float2 vs_[8], vd_[8];
    #pragma unroll
    for (int nt = 0; nt < 8; ++nt) {
        vs_[nt] = *(const float2*)&asrc[nBase + nt * 8 + 2 * tig];
        vd_[nt] = *(const float2*)&adst[nBase + nt * 8 + 2 * tig];
    }

    #pragma unroll
    for (int mt = 0; mt < 2; ++mt) {
        int r0 = mBase + w * 32 + mt * 16 + gid;   // row of d[0],d[1]
        int r1 = r0 + 8;                           // row of d[2],d[3]

        float sl = 0.f, dl = 0.f, sh = 0.f, dh = 0.f;
        #pragma unroll
        for (int nt = 0; nt < 8; ++nt) {
            sl += dacc[mt][nt][0] * vs_[nt].x + dacc[mt][nt][1] * vs_[nt].y;
            dl += dacc[mt][nt][0] * vd_[nt].x + dacc[mt][nt][1] * vd_[nt].y;
            sh += dacc[mt][nt][2] * vs_[nt].x + dacc[mt][nt][3] * vs_[nt].y;
            dh += dacc[mt][nt][2] * vd_[nt].x + dacc[mt][nt][3] * vd_[nt].y;
        }
        // reduce across the 4 lanes of the tig group
        #pragma unroll
        for (int off = 1; off < 4; off <<= 1) {
            sl += __shfl_xor_sync(0xffffffffu, sl, off);
            dl += __shfl_xor_sync(0xffffffffu, dl, off);
            sh += __shfl_xor_sync(0xffffffffu, sh, off);
            dh += __shfl_xor_sync(0xffffffffu, dh, off);
        }
        if (tig == 0) {
            if (r0 < M) { ss[yoff + r0] = sl; ds[yoff + r0] = dl; }
            if (r1 < M) { ss[yoff + r1] = sh; ds[yoff + r1] = dh; }
        }

        // bf16 stores: one bf16x2 (4B) per ntile per row
        #pragma unroll
        for (int nt = 0; nt < 8; ++nt) {
            int col = nBase + nt * 8 + 2 * tig;
            if (r0 < M) {
                __nv_bfloat162 p = __floats2bfloat162_rn(dacc[mt][nt][0], dacc[mt][nt][1]);
                *(unsigned*)&Cb[(size_t)r0 * Nout + col] = *(unsigned*)&p;
            }
            if (r1 < M) {
                __nv_bfloat162 p = __floats2bfloat162_rn(dacc[mt][nt][2], dacc[mt][nt][3]);
                *(unsigned*)&Cb[(size_t)r1 * Nout + col] = *(unsigned*)&p;
            }
        }
    }
}

// ---------------- bf16 row loads ----------------
__device__ __forceinline__ float4 ldrow128(const __nv_bfloat16* base, int row, int lane) {
    uint2 u = ((const uint2*)(base + (size_t)row * 128))[lane];
    __nv_bfloat162 p0 = *(__nv_bfloat162*)&u.x;
    __nv_bfloat162 p1 = *(__nv_bfloat162*)&u.y;
    float2 f0 = __bfloat1622float2(p0);
    float2 f1 = __bfloat1622float2(p1);
    return make_float4(f0.x, f0.y, f1.x, f1.y);
}
__device__ __forceinline__ float2 ldrow64(const __nv_bfloat16* base, int row, int lane) {
    unsigned u = ((const unsigned*)(base + (size_t)row * 64))[lane];
    __nv_bfloat162 p = *(__nv_bfloat162*)&u;
    return __bfloat1622float2(p);
}

// ---------------- fused GAT aggregate + bias + ReLU + LayerNorm ----------------
template <int F, bool TWO>
__global__ void agg_kernel(const __nv_bfloat16* __restrict__ hbf,
                           const float* __restrict__ ssp, const float* __restrict__ dsp,
                           const float* __restrict__ bias,
                           const float* __restrict__ gamma,
                           const float* __restrict__ beta,
                           float* __restrict__ out) {
    constexpr int VL = F / 32;
    int warp = (blockIdx.x * blockDim.x + threadIdx.x) >> 5;
    int lane = threadIdx.x & 31;
    if (warp >= NN) return;
    int n = warp;
    float dsn = TWO ? (dsp[n] + dsp[n + NN]) : dsp[n];
    int s0 = g_rowptr[n], s1 = g_rowptr[n + 1];

    auto score = [&](int s) -> float {
        return TWO ? (ssp[s] + ssp[s + NN]) : ssp[s];
    };

    float acc[VL];
    float w = __expf(lrelu(score(n) + dsn));   // self loop
    float z = w;
    if constexpr (VL == 4) {
        float4 t = ldrow128(hbf, n, lane);
        acc[0] = w * t.x; acc[1] = w * t.y; acc[2] = w * t.z; acc[3] = w * t.w;
    } else {
        float2 t = ldrow64(hbf, n, lane);
        acc[0] = w * t.x; acc[1] = w * t.y;
    }

    int i = s0;
    for (; i + 4 <= s1; i += 4) {
        int s[4];
        s[0] = g_csrsrc[i]; s[1] = g_csrsrc[i + 1];
        s[2] = g_csrsrc[i + 2]; s[3] = g_csrsrc[i + 3];
        float wv[4];
        #pragma unroll
        for (int k = 0; k < 4; ++k) { wv[k] = __expf(lrelu(score(s[k]) + dsn)); z += wv[k]; }
        if constexpr (VL == 4) {
            float4 t0 = ldrow128(hbf, s[0], lane);
            float4 t1 = ldrow128(hbf, s[1], lane);
            float4 t2 = ldrow128(hbf, s[2], lane);
            float4 t3 = ldrow128(hbf, s[3], lane);
            acc[0] += wv[0]*t0.x + wv[1]*t1.x + wv[2]*t2.x + wv[3]*t3.x;
            acc[1] += wv[0]*t0.y + wv[1]*t1.y + wv[2]*t2.y + wv[3]*t3.y;
            acc[2] += wv[0]*t0.z + wv[1]*t1.z + wv[2]*t2.z + wv[3]*t3.z;
            acc[3] += wv[0]*t0.w + wv[1]*t1.w + wv[2]*t2.w + wv[3]*t3.w;
        } else {
            float2 t0 = ldrow64(hbf, s[0], lane);
            float2 t1 = ldrow64(hbf, s[1], lane);
            float2 t2 = ldrow64(hbf, s[2], lane);
            float2 t3 = ldrow64(hbf, s[3], lane);
            acc[0] += wv[0]*t0.x + wv[1]*t1.x + wv[2]*t2.x + wv[3]*t3.x;
            acc[1] += wv[0]*t0.y + wv[1]*t1.y + wv[2]*t2.y + wv[3]*t3.y;
        }
    }
    for (; i < s1; ++i) {
        int s = g_csrsrc[i];
        float ww = __expf(lrelu(score(s) + dsn));
        z += ww;
        if constexpr (VL == 4) {
            float4 t = ldrow128(hbf, s, lane);
            acc[0] += ww * t.x; acc[1] += ww * t.y; acc[2] += ww * t.z; acc[3] += ww * t.w;
        } else {
            float2 t = ldrow64(hbf, s, lane);
            acc[0] += ww * t.x; acc[1] += ww * t.y;
        }
    }

    float inv = 1.f / z;
    float v[VL];
    float sum = 0.f;
    #pragma unroll
    for (int j = 0; j < VL; ++j) {
        v[j] = fmaxf(acc[j] * inv + bias[lane * VL + j], 0.f);  // bias + ReLU
        sum += v[j];
    }
    #pragma unroll
    for (int off = 16; off > 0; off >>= 1)
        sum += __shfl_xor_sync(0xffffffffu, sum, off);
    float mean = sum * (1.f / F);
    float vs = 0.f;
    #pragma unroll
    for (int j = 0; j < VL; ++j) {
        float d = v[j] - mean;
        vs += d * d;
    }
    #pragma unroll
    for (int off = 16; off > 0; off >>= 1)
        vs += __shfl_xor_sync(0xffffffffu, vs, off);
    float var = vs * (1.f / F);
    float r = rsqrtf(var + 1e-5f);
    if constexpr (VL == 4) {
        float4 gv = ((const float4*)gamma)[lane];
        float4 bv = ((const float4*)beta)[lane];
        float4 o;
        o.x = gv.x * (v[0] - mean) * r + bv.x;
        o.y = gv.y * (v[1] - mean) * r + bv.y;
        o.z = gv.z * (v[2] - mean) * r + bv.z;
        o.w = gv.w * (v[3] - mean) * r + bv.w;
        ((float4*)&out[(size_t)n * F])[lane] = o;
    } else {
        float2 gv = ((const float2*)gamma)[lane];
        float2 bv = ((const float2*)beta)[lane];
        float2 o;
        o.x = gv.x * (v[0] - mean) * r + bv.x;
        o.y = gv.y * (v[1] - mean) * r + bv.y;
        ((float2*)&out[(size_t)n * F])[lane] = o;
    }
}

// ---------------- fused pool + head: one block per graph (batch is sorted) ----------------
__global__ void poolhead_kernel(const float* __restrict__ h, const int* __restrict__ batch,
                                const float* __restrict__ Wl, const float* __restrict__ bl,
                                const float* __restrict__ Wc, const float* __restrict__ bc,
                                float* __restrict__ out) {
    __shared__ float psum[4][F2];
    __shared__ float p[F2];
    __shared__ int range[2];
    __shared__ float red[2];
    int g = blockIdx.x;
    int t = threadIdx.x;
    int f = t & 63, q = t >> 6;

    if (t < 2) {
        int val = g + t;
        int lo = 0, hi = NN;
        while (lo < hi) {
            int mid = (lo + hi) >> 1;
            if (batch[mid] < val) lo = mid + 1; else hi = mid;
        }
        range[t] = lo;
    }
    __syncthreads();
    int lo = range[0], hi = range[1];

    float acc = 0.f;
    for (int n = lo + q; n < hi; n += 4) acc += h[(size_t)n * F2 + f];
    psum[q][f] = acc;
    __syncthreads();

    if (t < F2) {
        float cnt = (float)(hi - lo);
        float s = psum[0][t] + psum[1][t] + psum[2][t] + psum[3][t];
        p[t] = s / fmaxf(cnt, 1.f);
    }
    __syncthreads();

    if (t < F2) {
        float lin = bl[t];
        #pragma unroll 8
        for (int j = 0; j < F2; ++j) lin += p[j] * Wl[t * F2 + j];
        float part = lin * Wc[t];
        #pragma unroll
        for (int off = 16; off > 0; off >>= 1)
            part += __shfl_xor_sync(0xffffffffu, part, off);
        if ((t & 31) == 0) red[t >> 5] = part;
    }
    __syncthreads();
    if (t == 0) out[g] = red[0] + red[1] + bc[0];
}

// ---------------- launch ----------------
extern "C" void kernel_launch(void* const* d_in, const int* in_sizes, int n_in,
                              void* d_out, int out_size) {
    const float* x    = (const float*)d_in[0];
    const int*   ei   = (const int*)d_in[1];
    const int*   batch= (const int*)d_in[2];
    const float* W1   = (const float*)d_in[3];
    const float* a1s  = (const float*)d_in[4];
    const float* a1d  = (const float*)d_in[5];
    const float* b1   = (const float*)d_in[6];
    const float* g1   = (const float*)d_in[7];
    const float* be1  = (const float*)d_in[8];
    const float* W2   = (const float*)d_in[9];
    const float* a2s  = (const float*)d_in[10];
    const float* a2d  = (const float*)d_in[11];
    const float* b2   = (const float*)d_in[12];
    const float* g2   = (const float*)d_in[13];
    const float* be2  = (const float*)d_in[14];
    const float* Wl   = (const float*)d_in[15];
    const float* bl   = (const float*)d_in[16];
    const float* Wc   = (const float*)d_in[17];
    const float* bc   = (const float*)d_in[18];
    float* out = (float*)d_out;

    const int* src = ei;
    const int* dst = ei + EE;

    __nv_bfloat16* phbf;
    float *phb, *pss1, *pds1, *pss2, *pds2;
    cudaGetSymbolAddress((void**)&phbf, g_hbf);
    cudaGetSymbolAddress((void**)&phb,  g_hb);
    cudaGetSymbolAddress((void**)&pss1, g_ss1);
    cudaGetSymbolAddress((void**)&pds1, g_ds1);
    cudaGetSymbolAddress((void**)&pss2, g_ss2);
    cudaGetSymbolAddress((void**)&pds2, g_ds2);

    // side stream + fork/join events (created once; host-side objects only)
    static cudaStream_t s1 = nullptr;
    static cudaEvent_t eFork = nullptr, eJoin = nullptr;
    if (s1 == nullptr) {
        cudaStreamCreateWithFlags(&s1, cudaStreamNonBlocking);
        cudaEventCreateWithFlags(&eFork, cudaEventDisableTiming);
        cudaEventCreateWithFlags(&eJoin, cudaEventDisableTiming);
    }

    const int NB = (NN + 255) / 256;   // 157

    // fork: CSR build chain on s1, GEMM1 on main stream
    cudaEventRecord(eFork, 0);
    cudaStreamWaitEvent(s1, eFork, 0);

    count_kernel<<<(EE / 4 + 255) / 256, 256, 0, s1>>>(dst);
    scan_kernel<<<NB, 256, 0, s1>>>();
    scatter_kernel<<<(EE / 4 + 255) / 256, 256, 0, s1>>>(src, dst);
    cudaEventRecord(eJoin, s1);

    // layer 1 GEMM (independent of CSR)
    gemm_tf32<<<dim3((NN + 127) / 128, F1 / 64), 128>>>(
        x, W1, phbf, pss1, pds1, a1s, a1d, NN, F1, 128);

    // join: agg1 needs CSR + GEMM1
    cudaStreamWaitEvent(0, eJoin, 0);
    agg_kernel<F1, true><<<(NN * 32 + 255) / 256, 256>>>(phbf, pss1, pds1, b1, g1, be1, phb);

    // layer 2
    gemm_tf32<<<dim3((NN + 127) / 128, F2 / 64), 128>>>(
        phb, W2, phbf, pss2, pds2, a2s, a2d, NN, F2, 128);
    agg_kernel<F2, false><<<(NN * 32 + 255) / 256, 256>>>(phbf, pss2, pds2, b2, g2, be2, phb);

    // fused pool + head
    poolhead_kernel<<<GG, 256>>>(phb, batch, Wl, bl, Wc, bc, out);
}